// round 1
// baseline (speedup 1.0000x reference)
#include <cuda_runtime.h>
#include <cstdint>

// Problem constants
#define BATCH 8
#define L 512
#define D 512
#define OUTR 1536
#define OUTC 2560

// GEMM tiling
#define BM 128
#define BN 128
#define BK 8

// Scratch (static device memory; allocation-free per harness rules)
__device__ float g_S[3][BATCH * L * L];     // S / P per pair (8 MB each)
__device__ float g_r[3][2][BATCH * L];      // rX, rY per pair
__device__ float g_m[3][BATCH * L];         // row max per pair
__device__ float g_v[3][BATCH * D];         // b2a vector per pair

// ---------------------------------------------------------------------------
// r[b,i] = dot(M[b,i,:], w) ; one warp per row
// ---------------------------------------------------------------------------
__global__ void rowdot_kernel(const float* __restrict__ M, const float* __restrict__ w,
                              int pair, int side) {
    int warp = blockIdx.x * 8 + (threadIdx.x >> 5);
    int lane = threadIdx.x & 31;
    if (warp >= BATCH * L) return;
    const float* row = M + (size_t)warp * D;
    float s = 0.f;
#pragma unroll
    for (int t = 0; t < 4; t++) {
        int k = (t * 32 + lane) * 4;
        float4 x = *(const float4*)(row + k);
        float4 wv = *(const float4*)(w + k);
        s += x.x * wv.x + x.y * wv.y + x.z * wv.z + x.w * wv.w;
    }
#pragma unroll
    for (int o = 16; o; o >>= 1) s += __shfl_xor_sync(0xFFFFFFFFu, s, o);
    if (!lane) g_r[pair][side][warp] = s;
}

// ---------------------------------------------------------------------------
// S[b,i,j] = rX[b,i] + rY[b,j] + sum_k X[b,i,k]*wM[k]*Y[b,j,k]
// 128x128 tile, BK=8, 256 threads, 8x8 micro-tile
// ---------------------------------------------------------------------------
__global__ __launch_bounds__(256)
void gemm_s_kernel(const float* __restrict__ X, const float* __restrict__ Y,
                   const float* __restrict__ wM, int pair) {
    int b = blockIdx.z;
    int i0 = blockIdx.y * BM;
    int j0 = blockIdx.x * BN;
    __shared__ float As[BK][BM + 4];
    __shared__ float Bs[BK][BN + 4];
    int tid = threadIdx.x;
    int tx = tid & 15, ty = tid >> 4;
    const float* Xb = X + (size_t)b * L * D;
    const float* Yb = Y + (size_t)b * L * D;
    float acc[8][8] = {};
    int la_row = tid >> 1;
    int la_c4 = (tid & 1) * 4;

    for (int k0 = 0; k0 < D; k0 += BK) {
        float4 av = *(const float4*)(Xb + (size_t)(i0 + la_row) * D + k0 + la_c4);
        float4 wv = *(const float4*)(wM + k0 + la_c4);
        As[la_c4 + 0][la_row] = av.x * wv.x;
        As[la_c4 + 1][la_row] = av.y * wv.y;
        As[la_c4 + 2][la_row] = av.z * wv.z;
        As[la_c4 + 3][la_row] = av.w * wv.w;
        float4 bv = *(const float4*)(Yb + (size_t)(j0 + la_row) * D + k0 + la_c4);
        Bs[la_c4 + 0][la_row] = bv.x;
        Bs[la_c4 + 1][la_row] = bv.y;
        Bs[la_c4 + 2][la_row] = bv.z;
        Bs[la_c4 + 3][la_row] = bv.w;
        __syncthreads();
#pragma unroll
        for (int k = 0; k < BK; k++) {
            float a[8], bb[8];
            *(float4*)&a[0] = *(const float4*)&As[k][ty * 8];
            *(float4*)&a[4] = *(const float4*)&As[k][ty * 8 + 4];
            *(float4*)&bb[0] = *(const float4*)&Bs[k][tx * 8];
            *(float4*)&bb[4] = *(const float4*)&Bs[k][tx * 8 + 4];
#pragma unroll
            for (int u = 0; u < 8; u++)
#pragma unroll
                for (int v = 0; v < 8; v++) acc[u][v] += a[u] * bb[v];
        }
        __syncthreads();
    }

    const float* rX = &g_r[pair][0][b * L];
    const float* rY = &g_r[pair][1][b * L];
    int jb = j0 + tx * 8;
    float ry[8];
#pragma unroll
    for (int v = 0; v < 8; v++) ry[v] = rY[jb + v];
    float* Sp = g_S[pair] + (size_t)b * L * L;
#pragma unroll
    for (int u = 0; u < 8; u++) {
        int i = i0 + ty * 8 + u;
        float rx = rX[i];
        float4 c0 = make_float4(acc[u][0] + rx + ry[0], acc[u][1] + rx + ry[1],
                                acc[u][2] + rx + ry[2], acc[u][3] + rx + ry[3]);
        float4 c1 = make_float4(acc[u][4] + rx + ry[4], acc[u][5] + rx + ry[5],
                                acc[u][6] + rx + ry[6], acc[u][7] + rx + ry[7]);
        *(float4*)(Sp + (size_t)i * L + jb) = c0;
        *(float4*)(Sp + (size_t)i * L + jb + 4) = c1;
    }
}

// ---------------------------------------------------------------------------
// In-place row softmax of S, store rowmax. One warp per row.
// ---------------------------------------------------------------------------
__global__ void softmax_kernel(int pair) {
    int row = blockIdx.x * 8 + (threadIdx.x >> 5);
    int lane = threadIdx.x & 31;
    float* r = g_S[pair] + (size_t)row * L;
    float4 v[4];
    float mx = -1e30f;
#pragma unroll
    for (int t = 0; t < 4; t++) {
        v[t] = ((float4*)r)[t * 32 + lane];
        mx = fmaxf(mx, fmaxf(fmaxf(v[t].x, v[t].y), fmaxf(v[t].z, v[t].w)));
    }
#pragma unroll
    for (int o = 16; o; o >>= 1) mx = fmaxf(mx, __shfl_xor_sync(0xFFFFFFFFu, mx, o));
    float s = 0.f;
#pragma unroll
    for (int t = 0; t < 4; t++) {
        v[t].x = __expf(v[t].x - mx);
        v[t].y = __expf(v[t].y - mx);
        v[t].z = __expf(v[t].z - mx);
        v[t].w = __expf(v[t].w - mx);
        s += v[t].x + v[t].y + v[t].z + v[t].w;
    }
#pragma unroll
    for (int o = 16; o; o >>= 1) s += __shfl_xor_sync(0xFFFFFFFFu, s, o);
    float inv = 1.f / s;
#pragma unroll
    for (int t = 0; t < 4; t++) {
        v[t].x *= inv; v[t].y *= inv; v[t].z *= inv; v[t].w *= inv;
        ((float4*)r)[t * 32 + lane] = v[t];
    }
    if (!lane) g_m[pair][row] = mx;
}

// ---------------------------------------------------------------------------
// C = P @ Y ; epilogue writes raw attention and enc*attention concat slices
// ---------------------------------------------------------------------------
__global__ __launch_bounds__(256)
void gemm_pv_kernel(const float* __restrict__ Y, const float* __restrict__ E,
                    float* __restrict__ out, int pair,
                    int secRow, int offRaw, int offProd) {
    int b = blockIdx.z;
    int i0 = blockIdx.y * BM;
    int d0 = blockIdx.x * BN;
    __shared__ float As[BK][BM + 4];
    __shared__ float Bs[BK][BN + 4];
    int tid = threadIdx.x;
    int tx = tid & 15, ty = tid >> 4;
    const float* Pb = g_S[pair] + (size_t)b * L * L;
    const float* Yb = Y + (size_t)b * L * D;
    float acc[8][8] = {};
    int la_row = tid >> 1;
    int la_c4 = (tid & 1) * 4;
    int lb_row = tid >> 5;
    int lb_c4 = (tid & 31) * 4;

    for (int j0 = 0; j0 < L; j0 += BK) {
        float4 av = *(const float4*)(Pb + (size_t)(i0 + la_row) * L + j0 + la_c4);
        As[la_c4 + 0][la_row] = av.x;
        As[la_c4 + 1][la_row] = av.y;
        As[la_c4 + 2][la_row] = av.z;
        As[la_c4 + 3][la_row] = av.w;
        float4 bv = *(const float4*)(Yb + (size_t)(j0 + lb_row) * D + d0 + lb_c4);
        *(float4*)&Bs[lb_row][lb_c4] = bv;
        __syncthreads();
#pragma unroll
        for (int k = 0; k < BK; k++) {
            float a[8], bb[8];
            *(float4*)&a[0] = *(const float4*)&As[k][ty * 8];
            *(float4*)&a[4] = *(const float4*)&As[k][ty * 8 + 4];
            *(float4*)&bb[0] = *(const float4*)&Bs[k][tx * 8];
            *(float4*)&bb[4] = *(const float4*)&Bs[k][tx * 8 + 4];
#pragma unroll
            for (int u = 0; u < 8; u++)
#pragma unroll
                for (int v = 0; v < 8; v++) acc[u][v] += a[u] * bb[v];
        }
        __syncthreads();
    }

    int db = d0 + tx * 8;
#pragma unroll
    for (int u = 0; u < 8; u++) {
        int i = i0 + ty * 8 + u;
        float* orow = out + ((size_t)b * OUTR + secRow + i) * OUTC;
        const float* erow = E + ((size_t)b * L + i) * D + db;
        float4 e0 = *(const float4*)(erow);
        float4 e1 = *(const float4*)(erow + 4);
        float4 c0 = make_float4(acc[u][0], acc[u][1], acc[u][2], acc[u][3]);
        float4 c1 = make_float4(acc[u][4], acc[u][5], acc[u][6], acc[u][7]);
        *(float4*)(orow + offRaw + db) = c0;
        *(float4*)(orow + offRaw + db + 4) = c1;
        float4 p0 = make_float4(c0.x * e0.x, c0.y * e0.y, c0.z * e0.z, c0.w * e0.w);
        float4 p1 = make_float4(c1.x * e1.x, c1.y * e1.y, c1.z * e1.z, c1.w * e1.w);
        *(float4*)(orow + offProd + db) = p0;
        *(float4*)(orow + offProd + db + 4) = p1;
    }
}

// ---------------------------------------------------------------------------
// beta = softmax_i(m[b,:]); v[b,d] = sum_i beta_i * X[b,i,d]. One block/batch.
// ---------------------------------------------------------------------------
__global__ __launch_bounds__(512)
void beta_b2a_kernel(const float* __restrict__ X, int pair) {
    int b = blockIdx.x, t = threadIdx.x;
    int lane = t & 31, wid = t >> 5;
    __shared__ float sb[512];
    __shared__ float redm[16];
    __shared__ float reds[16];
    __shared__ float bc[2];
    float mv = g_m[pair][b * L + t];
    float v = mv;
#pragma unroll
    for (int o = 16; o; o >>= 1) v = fmaxf(v, __shfl_xor_sync(0xFFFFFFFFu, v, o));
    if (!lane) redm[wid] = v;
    __syncthreads();
    if (t == 0) {
        float m2 = redm[0];
        for (int i = 1; i < 16; i++) m2 = fmaxf(m2, redm[i]);
        bc[0] = m2;
    }
    __syncthreads();
    float mx = bc[0];
    float e = __expf(mv - mx);
    v = e;
#pragma unroll
    for (int o = 16; o; o >>= 1) v += __shfl_xor_sync(0xFFFFFFFFu, v, o);
    if (!lane) reds[wid] = v;
    __syncthreads();
    if (t == 0) {
        float s = 0.f;
        for (int i = 0; i < 16; i++) s += reds[i];
        bc[1] = s;
    }
    __syncthreads();
    sb[t] = e / bc[1];
    __syncthreads();
    const float* Xb = X + (size_t)b * L * D;
    float acc = 0.f;
#pragma unroll 8
    for (int i = 0; i < L; i++) acc += sb[i] * Xb[(size_t)i * D + t];
    g_v[pair][b * D + t] = acc;
}

// ---------------------------------------------------------------------------
// Broadcast vector into out rows: raw + E*vec
// ---------------------------------------------------------------------------
__global__ void bcast_kernel(const float* __restrict__ E, float* __restrict__ out,
                             int pair, int secRow, int offRaw, int offProd) {
    int b = blockIdx.y, r = blockIdx.x;
    int t = threadIdx.x;  // 128 float4 lanes
    float4 vv = ((const float4*)(&g_v[pair][b * D]))[t];
    float4 ee = ((const float4*)(E + ((size_t)b * L + r) * D))[t];
    float* row = out + ((size_t)b * OUTR + secRow + r) * OUTC;
    ((float4*)(row + offRaw))[t] = vv;
    float4 p = make_float4(vv.x * ee.x, vv.y * ee.y, vv.z * ee.z, vv.w * ee.w);
    ((float4*)(row + offProd))[t] = p;
}

// ---------------------------------------------------------------------------
// Copy encoder into first 512 columns of its section
// ---------------------------------------------------------------------------
__global__ void copy_enc_kernel(const float* __restrict__ E, float* __restrict__ out,
                                int secRow) {
    int b = blockIdx.y, r = blockIdx.x;
    int t = threadIdx.x;
    float4 e = ((const float4*)(E + ((size_t)b * L + r) * D))[t];
    ((float4*)(out + ((size_t)b * OUTR + secRow + r) * OUTC))[t] = e;
}

// ---------------------------------------------------------------------------
extern "C" void kernel_launch(void* const* d_in, const int* in_sizes, int n_in,
                              void* d_out, int out_size) {
    const float* enc[3] = {(const float*)d_in[0], (const float*)d_in[1], (const float*)d_in[2]};
    const float* w[3] = {(const float*)d_in[3], (const float*)d_in[4], (const float*)d_in[5]};
    float* out = (float*)d_out;

    struct PairCfg {
        int xi, yi, wi;
        int secRowA, offRawA, offProdA;   // row-attention slice (X side section)
        int secRowV, offRawV, offProdV;   // broadcast-vector slice (Y side section)
    };
    const PairCfg cfg[3] = {
        {0, 1, 0,   0,  512, 1536,   512,  512, 1536},  // ab: a2b -> att_a, b2a -> att_b
        {0, 2, 1,   0, 1024, 2048,  1024,  512, 1536},  // ac: a2c -> att_a, c2a -> att_c
        {1, 2, 2, 512, 1024, 2048,  1024, 1024, 2048},  // bc: b2c -> att_b, c2b -> att_c
    };

    for (int p = 0; p < 3; p++) {
        const float* X = enc[cfg[p].xi];
        const float* Y = enc[cfg[p].yi];
        const float* ww = w[cfg[p].wi];
        rowdot_kernel<<<512, 256>>>(X, ww, p, 0);
        rowdot_kernel<<<512, 256>>>(Y, ww + 512, p, 1);
        gemm_s_kernel<<<dim3(4, 4, 8), 256>>>(X, Y, ww + 1024, p);
        softmax_kernel<<<512, 256>>>(p);
        gemm_pv_kernel<<<dim3(4, 4, 8), 256>>>(Y, X, out, p,
                                               cfg[p].secRowA, cfg[p].offRawA, cfg[p].offProdA);
        beta_b2a_kernel<<<8, 512>>>(X, p);
        bcast_kernel<<<dim3(512, 8), 128>>>(Y, out, p,
                                            cfg[p].secRowV, cfg[p].offRawV, cfg[p].offProdV);
    }
    copy_enc_kernel<<<dim3(512, 8), 128>>>(enc[0], out, 0);
    copy_enc_kernel<<<dim3(512, 8), 128>>>(enc[1], out, 512);
    copy_enc_kernel<<<dim3(512, 8), 128>>>(enc[2], out, 1024);
}

// round 4
// speedup vs baseline: 1.7112x; 1.7112x over previous
#include <cuda_runtime.h>
#include <cstdint>

#define BATCH 8
#define L 512
#define D 512
#define OUTR 1536
#define OUTC 2560
#define NCHUNK 16
#define LDA 36     // [row][k] smem stride (floats)
#define LDBPV 136  // [k][n] smem stride for PV B (floats)

// Scratch (static device memory; allocation-free per harness rules)
__device__ float g_S[3][BATCH * L * L];     // S / P per pair
__device__ float g_r[3][2][BATCH * L];      // rX, rY per pair
__device__ float g_m[3][BATCH * L];         // row max per pair
__device__ float g_v[3][BATCH * D];         // b2a vector per pair

// ===========================================================================
// mma.sync tf32 helpers (baseline PTX, works at compute_103)
// ===========================================================================
__device__ __forceinline__ uint32_t f2tf(float f) {
    uint32_t r;
    asm("cvt.rna.tf32.f32 %0, %1;" : "=r"(r) : "f"(f));
    return r;
}
__device__ __forceinline__ float4 cvt4(float4 v) {
    v.x = __uint_as_float(f2tf(v.x));
    v.y = __uint_as_float(f2tf(v.y));
    v.z = __uint_as_float(f2tf(v.z));
    v.w = __uint_as_float(f2tf(v.w));
    return v;
}
__device__ __forceinline__ void mma8(float* c, const uint32_t* a, const uint32_t* b) {
    asm volatile(
        "mma.sync.aligned.m16n8k8.row.col.f32.tf32.tf32.f32 "
        "{%0,%1,%2,%3}, {%4,%5,%6,%7}, {%8,%9}, {%0,%1,%2,%3};"
        : "+f"(c[0]), "+f"(c[1]), "+f"(c[2]), "+f"(c[3])
        : "r"(a[0]), "r"(a[1]), "r"(a[2]), "r"(a[3]), "r"(b[0]), "r"(b[1]));
}

// ===========================================================================
// S GEMM: S[b,i,j] = rX[i] + rY[j] + sum_k X[i,k] wM[k] Y[j,k]
// A smem [m][k] (128x36), B smem [j][k] (128x36)
// ===========================================================================
__global__ __launch_bounds__(256)
void gemm_s_mma(const float* __restrict__ X, const float* __restrict__ Y,
                const float* __restrict__ wM, int pair) {
    extern __shared__ float sm[];
    float* As = sm;                      // 2 * 128*LDA
    float* Bs = sm + 2 * 128 * LDA;      // 2 * 128*LDA
    int b = blockIdx.z, i0 = blockIdx.y * 128, j0 = blockIdx.x * 128;
    const float* Ag = X + ((size_t)b * L + i0) * D;
    const float* Bg = Y + ((size_t)b * L + j0) * D;
    int tid = threadIdx.x;
    int lrow = tid >> 1;
    int lcol = (tid & 1) * 16;

    int lane = tid & 31, w = tid >> 5;
    int ar = lane >> 2, ac = lane & 3;
    int mbase = (w & 1) * 64, nbase = (w >> 1) * 32;
    float acc[4][4][4] = {};
    float4 ra[4], rb[4];

#pragma unroll
    for (int q = 0; q < 4; q++) {
        float4 v = *(const float4*)(Ag + (size_t)lrow * D + lcol + q * 4);
        float4 wv = *(const float4*)(wM + lcol + q * 4);
        v.x *= wv.x; v.y *= wv.y; v.z *= wv.z; v.w *= wv.w;
        ra[q] = cvt4(v);
        rb[q] = cvt4(*(const float4*)(Bg + (size_t)lrow * D + lcol + q * 4));
    }
    {
        float* ap = As + lrow * LDA + lcol;
        float* bp = Bs + lrow * LDA + lcol;
#pragma unroll
        for (int q = 0; q < 4; q++) { *(float4*)(ap + q * 4) = ra[q]; *(float4*)(bp + q * 4) = rb[q]; }
    }
    __syncthreads();

    for (int c = 0; c < NCHUNK; c++) {
        if (c + 1 < NCHUNK) {
            int k0 = (c + 1) * 32;
#pragma unroll
            for (int q = 0; q < 4; q++) {
                float4 v = *(const float4*)(Ag + (size_t)lrow * D + k0 + lcol + q * 4);
                float4 wv = *(const float4*)(wM + k0 + lcol + q * 4);
                v.x *= wv.x; v.y *= wv.y; v.z *= wv.z; v.w *= wv.w;
                ra[q] = cvt4(v);
                rb[q] = cvt4(*(const float4*)(Bg + (size_t)lrow * D + k0 + lcol + q * 4));
            }
        }
        const float* a_s = As + (c & 1) * 128 * LDA;
        const float* b_s = Bs + (c & 1) * 128 * LDA;
#pragma unroll
        for (int ks = 0; ks < 4; ks++) {
            int k0 = ks * 8;
            uint32_t af[4][4], bf[4][2];
#pragma unroll
            for (int mt = 0; mt < 4; mt++) {
                const float* p = a_s + (mbase + mt * 16 + ar) * LDA + k0 + ac;
                af[mt][0] = __float_as_uint(p[0]);
                af[mt][1] = __float_as_uint(p[8 * LDA]);
                af[mt][2] = __float_as_uint(p[4]);
                af[mt][3] = __float_as_uint(p[8 * LDA + 4]);
            }
#pragma unroll
            for (int nt = 0; nt < 4; nt++) {
                const float* p = b_s + (nbase + nt * 8 + ar) * LDA + k0 + ac;
                bf[nt][0] = __float_as_uint(p[0]);
                bf[nt][1] = __float_as_uint(p[4]);
            }
#pragma unroll
            for (int mt = 0; mt < 4; mt++)
#pragma unroll
                for (int nt = 0; nt < 4; nt++) mma8(acc[mt][nt], af[mt], bf[nt]);
        }
        __syncthreads();
        if (c + 1 < NCHUNK) {
            float* ap = As + ((c + 1) & 1) * 128 * LDA + lrow * LDA + lcol;
            float* bp = Bs + ((c + 1) & 1) * 128 * LDA + lrow * LDA + lcol;
#pragma unroll
            for (int q = 0; q < 4; q++) { *(float4*)(ap + q * 4) = ra[q]; *(float4*)(bp + q * 4) = rb[q]; }
            __syncthreads();
        }
    }

    const float* rx = g_r[pair][0] + b * L + i0;
    const float* ry = g_r[pair][1] + b * L + j0;
    float* Sp = g_S[pair] + ((size_t)b * L + i0) * L + j0;
#pragma unroll
    for (int mt = 0; mt < 4; mt++) {
        int r = mbase + mt * 16 + ar;
        float rx0 = rx[r], rx1 = rx[r + 8];
#pragma unroll
        for (int nt = 0; nt < 4; nt++) {
            int cI = nbase + nt * 8 + ac * 2;
            float ry0 = ry[cI], ry1 = ry[cI + 1];
            float2 v0 = make_float2(acc[mt][nt][0] + rx0 + ry0, acc[mt][nt][1] + rx0 + ry1);
            float2 v1 = make_float2(acc[mt][nt][2] + rx1 + ry0, acc[mt][nt][3] + rx1 + ry1);
            *(float2*)(Sp + (size_t)r * L + cI) = v0;
            *(float2*)(Sp + (size_t)(r + 8) * L + cI) = v1;
        }
    }
}

// ===========================================================================
// PV GEMM: O[b,i,d] = sum_j P[i,j] Y[j,d]; fused concat writes (raw + E*O)
// A smem [i][j] (128x36), B smem [j][d] (32x136)
// ===========================================================================
__global__ __launch_bounds__(256)
void gemm_pv_mma(const float* __restrict__ Y, const float* __restrict__ E,
                 float* __restrict__ out, int pair,
                 int secRow, int offRaw, int offProd) {
    extern __shared__ float sm[];
    float* As = sm;                      // 2 * 128*LDA
    float* Bs = sm + 2 * 128 * LDA;      // 2 * 32*LDBPV
    int b = blockIdx.z, i0 = blockIdx.y * 128, d0 = blockIdx.x * 128;
    const float* Ag = g_S[pair] + ((size_t)b * L + i0) * L;
    const float* Bg = Y + (size_t)b * L * D + d0;
    int tid = threadIdx.x;
    int larow = tid >> 1;
    int lacol = (tid & 1) * 16;
    int lbrow = tid >> 3;
    int lbcol = (tid & 7) * 16;

    int lane = tid & 31, w = tid >> 5;
    int ar = lane >> 2, ac = lane & 3;
    int mbase = (w & 1) * 64, nbase = (w >> 1) * 32;
    float acc[4][4][4] = {};
    float4 ra[4], rb[4];

#pragma unroll
    for (int q = 0; q < 4; q++) {
        ra[q] = cvt4(*(const float4*)(Ag + (size_t)larow * L + lacol + q * 4));
        rb[q] = cvt4(*(const float4*)(Bg + (size_t)lbrow * D + lbcol + q * 4));
    }
    {
        float* ap = As + larow * LDA + lacol;
        float* bp = Bs + lbrow * LDBPV + lbcol;
#pragma unroll
        for (int q = 0; q < 4; q++) { *(float4*)(ap + q * 4) = ra[q]; *(float4*)(bp + q * 4) = rb[q]; }
    }
    __syncthreads();

    for (int c = 0; c < NCHUNK; c++) {
        if (c + 1 < NCHUNK) {
            int k0 = (c + 1) * 32;
#pragma unroll
            for (int q = 0; q < 4; q++) {
                ra[q] = cvt4(*(const float4*)(Ag + (size_t)larow * L + k0 + lacol + q * 4));
                rb[q] = cvt4(*(const float4*)(Bg + (size_t)(k0 + lbrow) * D + lbcol + q * 4));
            }
        }
        const float* a_s = As + (c & 1) * 128 * LDA;
        const float* b_s = Bs + (c & 1) * 32 * LDBPV;
#pragma unroll
        for (int ks = 0; ks < 4; ks++) {
            int k0 = ks * 8;
            uint32_t af[4][4], bf[4][2];
#pragma unroll
            for (int mt = 0; mt < 4; mt++) {
                const float* p = a_s + (mbase + mt * 16 + ar) * LDA + k0 + ac;
                af[mt][0] = __float_as_uint(p[0]);
                af[mt][1] = __float_as_uint(p[8 * LDA]);
                af[mt][2] = __float_as_uint(p[4]);
                af[mt][3] = __float_as_uint(p[8 * LDA + 4]);
            }
#pragma unroll
            for (int nt = 0; nt < 4; nt++) {
                const float* p = b_s + (k0 + ac) * LDBPV + nbase + nt * 8 + ar;
                bf[nt][0] = __float_as_uint(p[0]);
                bf[nt][1] = __float_as_uint(p[4 * LDBPV]);
            }
#pragma unroll
            for (int mt = 0; mt < 4; mt++)
#pragma unroll
                for (int nt = 0; nt < 4; nt++) mma8(acc[mt][nt], af[mt], bf[nt]);
        }
        __syncthreads();
        if (c + 1 < NCHUNK) {
            float* ap = As + ((c + 1) & 1) * 128 * LDA + larow * LDA + lacol;
            float* bp = Bs + ((c + 1) & 1) * 32 * LDBPV + lbrow * LDBPV + lbcol;
#pragma unroll
            for (int q = 0; q < 4; q++) { *(float4*)(ap + q * 4) = ra[q]; *(float4*)(bp + q * 4) = rb[q]; }
            __syncthreads();
        }
    }

#pragma unroll
    for (int mt = 0; mt < 4; mt++) {
        int r = mbase + mt * 16 + ar;
        int i = i0 + r;
        const float* e0p = E + ((size_t)b * L + i) * D + d0;
        float* o0p = out + ((size_t)b * OUTR + secRow + i) * OUTC;
#pragma unroll
        for (int nt = 0; nt < 4; nt++) {
            int cI = nbase + nt * 8 + ac * 2;
            float2 e0 = *(const float2*)(e0p + cI);
            float2 e1 = *(const float2*)(e0p + 8 * D + cI);
            float2 v0 = make_float2(acc[mt][nt][0], acc[mt][nt][1]);
            float2 v1 = make_float2(acc[mt][nt][2], acc[mt][nt][3]);
            *(float2*)(o0p + offRaw + d0 + cI) = v0;
            *(float2*)(o0p + 8 * OUTC + offRaw + d0 + cI) = v1;
            *(float2*)(o0p + offProd + d0 + cI) = make_float2(v0.x * e0.x, v0.y * e0.y);
            *(float2*)(o0p + 8 * OUTC + offProd + d0 + cI) = make_float2(v1.x * e1.x, v1.y * e1.y);
        }
    }
}

// ===========================================================================
// r[b,i] = dot(M[b,i,:], w) ; one warp per row
// ===========================================================================
__global__ void rowdot_kernel(const float* __restrict__ M, const float* __restrict__ w,
                              int pair, int side) {
    int warp = blockIdx.x * 8 + (threadIdx.x >> 5);
    int lane = threadIdx.x & 31;
    if (warp >= BATCH * L) return;
    const float* row = M + (size_t)warp * D;
    float s = 0.f;
#pragma unroll
    for (int t = 0; t < 4; t++) {
        int k = (t * 32 + lane) * 4;
        float4 x = *(const float4*)(row + k);
        float4 wv = *(const float4*)(w + k);
        s += x.x * wv.x + x.y * wv.y + x.z * wv.z + x.w * wv.w;
    }
#pragma unroll
    for (int o = 16; o; o >>= 1) s += __shfl_xor_sync(0xFFFFFFFFu, s, o);
    if (!lane) g_r[pair][side][warp] = s;
}

// ===========================================================================
// In-place row softmax of S, store rowmax. One warp per row.
// ===========================================================================
__global__ void softmax_kernel(int pair) {
    int row = blockIdx.x * 8 + (threadIdx.x >> 5);
    int lane = threadIdx.x & 31;
    float* r = g_S[pair] + (size_t)row * L;
    float4 v[4];
    float mx = -1e30f;
#pragma unroll
    for (int t = 0; t < 4; t++) {
        v[t] = ((float4*)r)[t * 32 + lane];
        mx = fmaxf(mx, fmaxf(fmaxf(v[t].x, v[t].y), fmaxf(v[t].z, v[t].w)));
    }
#pragma unroll
    for (int o = 16; o; o >>= 1) mx = fmaxf(mx, __shfl_xor_sync(0xFFFFFFFFu, mx, o));
    float s = 0.f;
#pragma unroll
    for (int t = 0; t < 4; t++) {
        v[t].x = __expf(v[t].x - mx);
        v[t].y = __expf(v[t].y - mx);
        v[t].z = __expf(v[t].z - mx);
        v[t].w = __expf(v[t].w - mx);
        s += v[t].x + v[t].y + v[t].z + v[t].w;
    }
#pragma unroll
    for (int o = 16; o; o >>= 1) s += __shfl_xor_sync(0xFFFFFFFFu, s, o);
    float inv = 1.f / s;
#pragma unroll
    for (int t = 0; t < 4; t++) {
        v[t].x *= inv; v[t].y *= inv; v[t].z *= inv; v[t].w *= inv;
        ((float4*)r)[t * 32 + lane] = v[t];
    }
    if (!lane) g_m[pair][row] = mx;
}

// ===========================================================================
// beta = softmax_i(m[b,:]); v[b,d] = sum_i beta_i * X[b,i,d]. One block/batch.
// ===========================================================================
__global__ __launch_bounds__(512)
void beta_b2a_kernel(const float* __restrict__ X, int pair) {
    int b = blockIdx.x, t = threadIdx.x;
    int lane = t & 31, wid = t >> 5;
    __shared__ float sb[512];
    __shared__ float redm[16];
    __shared__ float reds[16];
    __shared__ float bc[2];
    float mv = g_m[pair][b * L + t];
    float v = mv;
#pragma unroll
    for (int o = 16; o; o >>= 1) v = fmaxf(v, __shfl_xor_sync(0xFFFFFFFFu, v, o));
    if (!lane) redm[wid] = v;
    __syncthreads();
    if (t == 0) {
        float m2 = redm[0];
        for (int i = 1; i < 16; i++) m2 = fmaxf(m2, redm[i]);
        bc[0] = m2;
    }
    __syncthreads();
    float mx = bc[0];
    float e = __expf(mv - mx);
    v = e;
#pragma unroll
    for (int o = 16; o; o >>= 1) v += __shfl_xor_sync(0xFFFFFFFFu, v, o);
    if (!lane) reds[wid] = v;
    __syncthreads();
    if (t == 0) {
        float s = 0.f;
        for (int i = 0; i < 16; i++) s += reds[i];
        bc[1] = s;
    }
    __syncthreads();
    sb[t] = e / bc[1];
    __syncthreads();
    const float* Xb = X + (size_t)b * L * D;
    float acc = 0.f;
#pragma unroll 8
    for (int i = 0; i < L; i++) acc += sb[i] * Xb[(size_t)i * D + t];
    g_v[pair][b * D + t] = acc;
}

// ===========================================================================
// Broadcast vector into out rows: raw + E*vec
// ===========================================================================
__global__ void bcast_kernel(const float* __restrict__ E, float* __restrict__ out,
                             int pair, int secRow, int offRaw, int offProd) {
    int b = blockIdx.y, r = blockIdx.x;
    int t = threadIdx.x;
    float4 vv = ((const float4*)(&g_v[pair][b * D]))[t];
    float4 ee = ((const float4*)(E + ((size_t)b * L + r) * D))[t];
    float* row = out + ((size_t)b * OUTR + secRow + r) * OUTC;
    ((float4*)(row + offRaw))[t] = vv;
    float4 p = make_float4(vv.x * ee.x, vv.y * ee.y, vv.z * ee.z, vv.w * ee.w);
    ((float4*)(row + offProd))[t] = p;
}

// ===========================================================================
// Copy encoder into first 512 columns of its section
// ===========================================================================
__global__ void copy_enc_kernel(const float* __restrict__ E, float* __restrict__ out,
                                int secRow) {
    int b = blockIdx.y, r = blockIdx.x;
    int t = threadIdx.x;
    float4 e = ((const float4*)(E + ((size_t)b * L + r) * D))[t];
    ((float4*)(out + ((size_t)b * OUTR + secRow + r) * OUTC))[t] = e;
}

// ===========================================================================
#define SMEM_S  (2 * 128 * LDA * 4 * 2)                     // 73728 B
#define SMEM_PV ((2 * 128 * LDA + 2 * 32 * LDBPV) * 4)      // 71680 B

extern "C" void kernel_launch(void* const* d_in, const int* in_sizes, int n_in,
                              void* d_out, int out_size) {
    const float* enc[3] = {(const float*)d_in[0], (const float*)d_in[1], (const float*)d_in[2]};
    const float* w[3] = {(const float*)d_in[3], (const float*)d_in[4], (const float*)d_in[5]};
    float* out = (float*)d_out;

    cudaFuncSetAttribute(gemm_s_mma, cudaFuncAttributeMaxDynamicSharedMemorySize, SMEM_S);
    cudaFuncSetAttribute(gemm_pv_mma, cudaFuncAttributeMaxDynamicSharedMemorySize, SMEM_PV);

    struct PairCfg {
        int xi, yi, wi;
        int secRowA, offRawA, offProdA;
        int secRowV, offRawV, offProdV;
    };
    const PairCfg cfg[3] = {
        {0, 1, 0,   0,  512, 1536,   512,  512, 1536},  // ab
        {0, 2, 1,   0, 1024, 2048,  1024,  512, 1536},  // ac
        {1, 2, 2, 512, 1024, 2048,  1024, 1024, 2048},  // bc
    };

    for (int p = 0; p < 3; p++) {
        const float* X = enc[cfg[p].xi];
        const float* Y = enc[cfg[p].yi];
        const float* ww = w[cfg[p].wi];
        rowdot_kernel<<<512, 256>>>(X, ww, p, 0);
        rowdot_kernel<<<512, 256>>>(Y, ww + 512, p, 1);
        gemm_s_mma<<<dim3(4, 4, 8), 256, SMEM_S>>>(X, Y, ww + 1024, p);
        softmax_kernel<<<512, 256>>>(p);
        gemm_pv_mma<<<dim3(4, 4, 8), 256, SMEM_PV>>>(Y, X, out, p,
                                                     cfg[p].secRowA, cfg[p].offRawA, cfg[p].offProdA);
        beta_b2a_kernel<<<8, 512>>>(X, p);
        bcast_kernel<<<dim3(512, 8), 128>>>(Y, out, p,
                                            cfg[p].secRowV, cfg[p].offRawV, cfg[p].offProdV);
    }
    copy_enc_kernel<<<dim3(512, 8), 128>>>(enc[0], out, 0);
    copy_enc_kernel<<<dim3(512, 8), 128>>>(enc[1], out, 512);
    copy_enc_kernel<<<dim3(512, 8), 128>>>(enc[2], out, 1024);
}

// round 5
// speedup vs baseline: 3.1070x; 1.8156x over previous
#include <cuda_runtime.h>
#include <cstdint>

#define BATCH 8
#define L 512
#define D 512
#define OUTR 1536
#define OUTC 2560
#define NCHUNK 16
#define LDA 36     // [row][k] smem stride (floats)
#define LDBPV 136  // [k][n] smem stride for PV B (floats)

// Stage sizes (floats)
#define STAGE_S  (2 * 128 * LDA)              // 9216  (A 128x36 + B 128x36)
#define STAGE_PV (128 * LDA + 32 * LDBPV)     // 8960  (A 128x36 + B 32x136)
#define SMEM_S   (3 * STAGE_S * 4)            // 110592 B
#define SMEM_PV  (3 * STAGE_PV * 4)           // 107520 B

// Scratch (static device memory; allocation-free per harness rules)
__device__ float g_S[3][BATCH * L * L];     // S / P per pair (P stored tf32-rounded)
__device__ float g_Xw[3][BATCH * L * D];    // tf32(X * wM) per pair
__device__ float g_Yc[2][BATCH * L * D];    // tf32(enc_b), tf32(enc_c)
__device__ float g_r[3][2][BATCH * L];      // rX, rY per pair
__device__ float g_m[3][BATCH * L];         // row max per pair
__device__ float g_v[3][BATCH * D];         // b2a vector per pair

// ===========================================================================
// helpers
// ===========================================================================
__device__ __forceinline__ uint32_t f2tf(float f) {
    uint32_t r;
    asm("cvt.rna.tf32.f32 %0, %1;" : "=r"(r) : "f"(f));
    return r;
}
__device__ __forceinline__ float4 cvt4(float4 v) {
    v.x = __uint_as_float(f2tf(v.x));
    v.y = __uint_as_float(f2tf(v.y));
    v.z = __uint_as_float(f2tf(v.z));
    v.w = __uint_as_float(f2tf(v.w));
    return v;
}
__device__ __forceinline__ void mma8(float* c, const uint32_t* a, const uint32_t* b) {
    asm volatile(
        "mma.sync.aligned.m16n8k8.row.col.f32.tf32.tf32.f32 "
        "{%0,%1,%2,%3}, {%4,%5,%6,%7}, {%8,%9}, {%0,%1,%2,%3};"
        : "+f"(c[0]), "+f"(c[1]), "+f"(c[2]), "+f"(c[3])
        : "r"(a[0]), "r"(a[1]), "r"(a[2]), "r"(a[3]), "r"(b[0]), "r"(b[1]));
}
__device__ __forceinline__ void cp16(float* dst, const float* src) {
    uint32_t d = (uint32_t)__cvta_generic_to_shared(dst);
    asm volatile("cp.async.cg.shared.global [%0], [%1], 16;" :: "r"(d), "l"(src) : "memory");
}
__device__ __forceinline__ void cp_commit() {
    asm volatile("cp.async.commit_group;" ::: "memory");
}

// ===========================================================================
// prep: per encoder matrix, one pass: 2 row-dots + tf32-converted operand copies
// grid (512, 3), 256 threads (8 warps, 1 row/warp)
// ===========================================================================
__global__ void prep_kernel(const float* __restrict__ ea, const float* __restrict__ eb,
                            const float* __restrict__ ec,
                            const float* __restrict__ wab, const float* __restrict__ wac,
                            const float* __restrict__ wbc) {
    int mat = blockIdx.y;
    int row = blockIdx.x * 8 + (threadIdx.x >> 5);
    int lane = threadIdx.x & 31;

    const float *src, *w1, *w2, *sc1, *sc2;
    float *r1, *r2, *d1, *d2;
    if (mat == 0) {
        src = ea; w1 = wab; r1 = &g_r[0][0][0]; w2 = wac; r2 = &g_r[1][0][0];
        sc1 = wab + 1024; d1 = g_Xw[0]; sc2 = wac + 1024; d2 = g_Xw[1];
    } else if (mat == 1) {
        src = eb; w1 = wab + 512; r1 = &g_r[0][1][0]; w2 = wbc; r2 = &g_r[2][0][0];
        sc1 = wbc + 1024; d1 = g_Xw[2]; sc2 = nullptr; d2 = g_Yc[0];
    } else {
        src = ec; w1 = wac + 512; r1 = &g_r[1][1][0]; w2 = wbc + 512; r2 = &g_r[2][1][0];
        sc1 = nullptr; d1 = g_Yc[1]; sc2 = nullptr; d2 = nullptr;
    }

    const float* rp = src + (size_t)row * D;
    float4 x[4];
    float s1 = 0.f, s2 = 0.f;
#pragma unroll
    for (int t = 0; t < 4; t++) {
        int k = (t * 32 + lane) * 4;
        x[t] = *(const float4*)(rp + k);
        float4 a = *(const float4*)(w1 + k);
        s1 += x[t].x * a.x + x[t].y * a.y + x[t].z * a.z + x[t].w * a.w;
        float4 b = *(const float4*)(w2 + k);
        s2 += x[t].x * b.x + x[t].y * b.y + x[t].z * b.z + x[t].w * b.w;
    }
#pragma unroll
    for (int o = 16; o; o >>= 1) {
        s1 += __shfl_xor_sync(0xFFFFFFFFu, s1, o);
        s2 += __shfl_xor_sync(0xFFFFFFFFu, s2, o);
    }
    if (!lane) { r1[row] = s1; r2[row] = s2; }

#pragma unroll
    for (int t = 0; t < 4; t++) {
        int k = (t * 32 + lane) * 4;
        float4 v = x[t];
        if (sc1) {
            float4 s = *(const float4*)(sc1 + k);
            v.x *= s.x; v.y *= s.y; v.z *= s.z; v.w *= s.w;
        }
        *(float4*)(d1 + (size_t)row * D + k) = cvt4(v);
    }
    if (d2) {
#pragma unroll
        for (int t = 0; t < 4; t++) {
            int k = (t * 32 + lane) * 4;
            float4 v = x[t];
            if (sc2) {
                float4 s = *(const float4*)(sc2 + k);
                v.x *= s.x; v.y *= s.y; v.z *= s.z; v.w *= s.w;
            }
            *(float4*)(d2 + (size_t)row * D + k) = cvt4(v);
        }
    }
}

// ===========================================================================
// S GEMM (batched pairs): S = rX + rY + Xw @ Yc^T
// grid (4,4,24) z = pair*8 + b
// ===========================================================================
__global__ __launch_bounds__(256, 2)
void gemm_s_mma(const float* __restrict__ dummy) {
    extern __shared__ float sm[];
    int pair = blockIdx.z >> 3, b = blockIdx.z & 7;
    int yt = (pair == 0) ? 0 : 1;
    int i0 = blockIdx.y * 128, j0 = blockIdx.x * 128;
    const float* Ag = g_Xw[pair] + ((size_t)b * L + i0) * D;
    const float* Bg = g_Yc[yt] + ((size_t)b * L + j0) * D;
    int tid = threadIdx.x;

    int lane = tid & 31, w = tid >> 5;
    int ar = lane >> 2, ac = lane & 3;
    int mbase = (w & 1) * 64, nbase = (w >> 1) * 32;
    float acc[4][4][4] = {};

    // issue helper (A tile 128x32 + B tile 128x32 into stage st)
    auto issue = [&](int c, int st) {
        float* As = sm + st * STAGE_S;
        float* Bs = As + 128 * LDA;
        int k0 = c * 32;
#pragma unroll
        for (int it = 0; it < 4; it++) {
            int i = it * 256 + tid;
            int row = i >> 3, c4 = (i & 7) << 2;
            cp16(As + row * LDA + c4, Ag + (size_t)row * D + k0 + c4);
            cp16(Bs + row * LDA + c4, Bg + (size_t)row * D + k0 + c4);
        }
        cp_commit();
    };

    issue(0, 0);
    issue(1, 1);
    int st_c = 0, st_n = 2;
    for (int c = 0; c < NCHUNK; c++) {
        if (c < NCHUNK - 1) asm volatile("cp.async.wait_group 1;" ::: "memory");
        else                asm volatile("cp.async.wait_group 0;" ::: "memory");
        __syncthreads();
        if (c + 2 < NCHUNK) issue(c + 2, st_n);
        const float* a_s = sm + st_c * STAGE_S;
        const float* b_s = a_s + 128 * LDA;
#pragma unroll
        for (int ks = 0; ks < 4; ks++) {
            int k0 = ks * 8;
            uint32_t af[4][4], bf[4][2];
#pragma unroll
            for (int mt = 0; mt < 4; mt++) {
                const float* p = a_s + (mbase + mt * 16 + ar) * LDA + k0 + ac;
                af[mt][0] = __float_as_uint(p[0]);
                af[mt][1] = __float_as_uint(p[8 * LDA]);
                af[mt][2] = __float_as_uint(p[4]);
                af[mt][3] = __float_as_uint(p[8 * LDA + 4]);
            }
#pragma unroll
            for (int nt = 0; nt < 4; nt++) {
                const float* p = b_s + (nbase + nt * 8 + ar) * LDA + k0 + ac;
                bf[nt][0] = __float_as_uint(p[0]);
                bf[nt][1] = __float_as_uint(p[4]);
            }
#pragma unroll
            for (int mt = 0; mt < 4; mt++)
#pragma unroll
                for (int nt = 0; nt < 4; nt++) mma8(acc[mt][nt], af[mt], bf[nt]);
        }
        st_c = (st_c == 2) ? 0 : st_c + 1;
        st_n = (st_n == 2) ? 0 : st_n + 1;
    }

    const float* rx = g_r[pair][0] + b * L + i0;
    const float* ry = g_r[pair][1] + b * L + j0;
    float* Sp = g_S[pair] + ((size_t)b * L + i0) * L + j0;
#pragma unroll
    for (int mt = 0; mt < 4; mt++) {
        int r = mbase + mt * 16 + ar;
        float rx0 = rx[r], rx1 = rx[r + 8];
#pragma unroll
        for (int nt = 0; nt < 4; nt++) {
            int cI = nbase + nt * 8 + ac * 2;
            float ry0 = ry[cI], ry1 = ry[cI + 1];
            float2 v0 = make_float2(acc[mt][nt][0] + rx0 + ry0, acc[mt][nt][1] + rx0 + ry1);
            float2 v1 = make_float2(acc[mt][nt][2] + rx1 + ry0, acc[mt][nt][3] + rx1 + ry1);
            *(float2*)(Sp + (size_t)r * L + cI) = v0;
            *(float2*)(Sp + (size_t)(r + 8) * L + cI) = v1;
        }
    }
}

// ===========================================================================
// PV GEMM (batched pairs): O = P @ Yc; fused concat writes (raw + E*O)
// ===========================================================================
__constant__ int c_secRowA[3] = {0, 0, 512};
__constant__ int c_offRawA[3] = {512, 1024, 1024};
__constant__ int c_offProdA[3] = {1536, 2048, 2048};

__global__ __launch_bounds__(256, 2)
void gemm_pv_mma(const float* __restrict__ ea, const float* __restrict__ eb,
                 const float* __restrict__ ec, float* __restrict__ out) {
    extern __shared__ float sm[];
    int pair = blockIdx.z >> 3, b = blockIdx.z & 7;
    int yt = (pair == 0) ? 0 : 1;
    const float* E = (pair == 2) ? eb : ea;
    int secRow = c_secRowA[pair], offRaw = c_offRawA[pair], offProd = c_offProdA[pair];
    int i0 = blockIdx.y * 128, d0 = blockIdx.x * 128;
    const float* Ag = g_S[pair] + ((size_t)b * L + i0) * L;
    const float* Bg = g_Yc[yt] + (size_t)b * L * D + d0;
    int tid = threadIdx.x;

    int lane = tid & 31, w = tid >> 5;
    int ar = lane >> 2, ac = lane & 3;
    int mbase = (w & 1) * 64, nbase = (w >> 1) * 32;
    float acc[4][4][4] = {};

    auto issue = [&](int c, int st) {
        float* As = sm + st * STAGE_PV;
        float* Bs = As + 128 * LDA;
        int k0 = c * 32;
#pragma unroll
        for (int it = 0; it < 4; it++) {
            int i = it * 256 + tid;
            int arow = i >> 3, ac4 = (i & 7) << 2;
            cp16(As + arow * LDA + ac4, Ag + (size_t)arow * L + k0 + ac4);
            int brow = i >> 5, bc4 = (i & 31) << 2;
            cp16(Bs + brow * LDBPV + bc4, Bg + (size_t)(k0 + brow) * D + bc4);
        }
        cp_commit();
    };

    issue(0, 0);
    issue(1, 1);
    int st_c = 0, st_n = 2;
    for (int c = 0; c < NCHUNK; c++) {
        if (c < NCHUNK - 1) asm volatile("cp.async.wait_group 1;" ::: "memory");
        else                asm volatile("cp.async.wait_group 0;" ::: "memory");
        __syncthreads();
        if (c + 2 < NCHUNK) issue(c + 2, st_n);
        const float* a_s = sm + st_c * STAGE_PV;
        const float* b_s = a_s + 128 * LDA;
#pragma unroll
        for (int ks = 0; ks < 4; ks++) {
            int k0 = ks * 8;
            uint32_t af[4][4], bf[4][2];
#pragma unroll
            for (int mt = 0; mt < 4; mt++) {
                const float* p = a_s + (mbase + mt * 16 + ar) * LDA + k0 + ac;
                af[mt][0] = __float_as_uint(p[0]);
                af[mt][1] = __float_as_uint(p[8 * LDA]);
                af[mt][2] = __float_as_uint(p[4]);
                af[mt][3] = __float_as_uint(p[8 * LDA + 4]);
            }
#pragma unroll
            for (int nt = 0; nt < 4; nt++) {
                const float* p = b_s + (k0 + ac) * LDBPV + nbase + nt * 8 + ar;
                bf[nt][0] = __float_as_uint(p[0]);
                bf[nt][1] = __float_as_uint(p[4 * LDBPV]);
            }
#pragma unroll
            for (int mt = 0; mt < 4; mt++)
#pragma unroll
                for (int nt = 0; nt < 4; nt++) mma8(acc[mt][nt], af[mt], bf[nt]);
        }
        st_c = (st_c == 2) ? 0 : st_c + 1;
        st_n = (st_n == 2) ? 0 : st_n + 1;
    }

#pragma unroll
    for (int mt = 0; mt < 4; mt++) {
        int r = mbase + mt * 16 + ar;
        int i = i0 + r;
        const float* e0p = E + ((size_t)b * L + i) * D + d0;
        float* o0p = out + ((size_t)b * OUTR + secRow + i) * OUTC;
#pragma unroll
        for (int nt = 0; nt < 4; nt++) {
            int cI = nbase + nt * 8 + ac * 2;
            float2 e0 = *(const float2*)(e0p + cI);
            float2 e1 = *(const float2*)(e0p + 8 * D + cI);
            float2 v0 = make_float2(acc[mt][nt][0], acc[mt][nt][1]);
            float2 v1 = make_float2(acc[mt][nt][2], acc[mt][nt][3]);
            *(float2*)(o0p + offRaw + d0 + cI) = v0;
            *(float2*)(o0p + 8 * OUTC + offRaw + d0 + cI) = v1;
            *(float2*)(o0p + offProd + d0 + cI) = make_float2(v0.x * e0.x, v0.y * e0.y);
            *(float2*)(o0p + 8 * OUTC + offProd + d0 + cI) = make_float2(v1.x * e1.x, v1.y * e1.y);
        }
    }
}

// ===========================================================================
// softmax (batched): in-place row softmax of S, P stored tf32-rounded; rowmax out
// grid (512, 3)
// ===========================================================================
__global__ void softmax_kernel(const float* __restrict__ dummy) {
    int pair = blockIdx.y;
    int row = blockIdx.x * 8 + (threadIdx.x >> 5);
    int lane = threadIdx.x & 31;
    float* r = g_S[pair] + (size_t)row * L;
    float4 v[4];
    float mx = -1e30f;
#pragma unroll
    for (int t = 0; t < 4; t++) {
        v[t] = ((float4*)r)[t * 32 + lane];
        mx = fmaxf(mx, fmaxf(fmaxf(v[t].x, v[t].y), fmaxf(v[t].z, v[t].w)));
    }
#pragma unroll
    for (int o = 16; o; o >>= 1) mx = fmaxf(mx, __shfl_xor_sync(0xFFFFFFFFu, mx, o));
    float s = 0.f;
#pragma unroll
    for (int t = 0; t < 4; t++) {
        v[t].x = __expf(v[t].x - mx);
        v[t].y = __expf(v[t].y - mx);
        v[t].z = __expf(v[t].z - mx);
        v[t].w = __expf(v[t].w - mx);
        s += v[t].x + v[t].y + v[t].z + v[t].w;
    }
#pragma unroll
    for (int o = 16; o; o >>= 1) s += __shfl_xor_sync(0xFFFFFFFFu, s, o);
    float inv = 1.f / s;
#pragma unroll
    for (int t = 0; t < 4; t++) {
        v[t].x *= inv; v[t].y *= inv; v[t].z *= inv; v[t].w *= inv;
        ((float4*)r)[t * 32 + lane] = cvt4(v[t]);
    }
    if (!lane) g_m[pair][row] = mx;
}

// ===========================================================================
// beta (batched): beta = softmax_i(m); v = sum_i beta_i * X[b,i,:]. grid (8,3)
// ===========================================================================
__global__ __launch_bounds__(512)
void beta_b2a_kernel(const float* __restrict__ ea, const float* __restrict__ eb,
                     const float* __restrict__ ec) {
    int b = blockIdx.x, pair = blockIdx.y, t = threadIdx.x;
    const float* X = (pair == 2) ? eb : ea;
    int lane = t & 31, wid = t >> 5;
    __shared__ float sb[512];
    __shared__ float redm[16];
    __shared__ float reds[16];
    __shared__ float bc[2];
    float mv = g_m[pair][b * L + t];
    float v = mv;
#pragma unroll
    for (int o = 16; o; o >>= 1) v = fmaxf(v, __shfl_xor_sync(0xFFFFFFFFu, v, o));
    if (!lane) redm[wid] = v;
    __syncthreads();
    if (t == 0) {
        float m2 = redm[0];
        for (int i = 1; i < 16; i++) m2 = fmaxf(m2, redm[i]);
        bc[0] = m2;
    }
    __syncthreads();
    float mx = bc[0];
    float e = __expf(mv - mx);
    v = e;
#pragma unroll
    for (int o = 16; o; o >>= 1) v += __shfl_xor_sync(0xFFFFFFFFu, v, o);
    if (!lane) reds[wid] = v;
    __syncthreads();
    if (t == 0) {
        float s = 0.f;
        for (int i = 0; i < 16; i++) s += reds[i];
        bc[1] = s;
    }
    __syncthreads();
    sb[t] = e / bc[1];
    __syncthreads();
    const float* Xb = X + (size_t)b * L * D;
    float acc = 0.f;
#pragma unroll 8
    for (int i = 0; i < L; i++) acc += sb[i] * Xb[(size_t)i * D + t];
    g_v[pair][b * D + t] = acc;
}

// ===========================================================================
// bcast (batched): broadcast vector rows (raw + E*vec). grid (512, 8, 3)
// ===========================================================================
__constant__ int c_secRowV[3] = {512, 1024, 1024};
__constant__ int c_offRawV[3] = {512, 512, 1024};
__constant__ int c_offProdV[3] = {1536, 1536, 2048};

__global__ void bcast_kernel(const float* __restrict__ ea, const float* __restrict__ eb,
                             const float* __restrict__ ec, float* __restrict__ out) {
    int pair = blockIdx.z, b = blockIdx.y, r = blockIdx.x;
    const float* E = (pair == 0) ? eb : ec;
    int t = threadIdx.x;
    float4 vv = ((const float4*)(&g_v[pair][b * D]))[t];
    float4 ee = ((const float4*)(E + ((size_t)b * L + r) * D))[t];
    float* row = out + ((size_t)b * OUTR + c_secRowV[pair] + r) * OUTC;
    ((float4*)(row + c_offRawV[pair]))[t] = vv;
    float4 p = make_float4(vv.x * ee.x, vv.y * ee.y, vv.z * ee.z, vv.w * ee.w);
    ((float4*)(row + c_offProdV[pair]))[t] = p;
}

// ===========================================================================
// copy encoders into first 512 columns. grid (512, 8, 3)
// ===========================================================================
__global__ void copy_enc_kernel(const float* __restrict__ ea, const float* __restrict__ eb,
                                const float* __restrict__ ec, float* __restrict__ out) {
    int which = blockIdx.z, b = blockIdx.y, r = blockIdx.x;
    const float* E = (which == 0) ? ea : (which == 1) ? eb : ec;
    int t = threadIdx.x;
    float4 e = ((const float4*)(E + ((size_t)b * L + r) * D))[t];
    ((float4*)(out + ((size_t)b * OUTR + which * 512 + r) * OUTC))[t] = e;
}

// ===========================================================================
extern "C" void kernel_launch(void* const* d_in, const int* in_sizes, int n_in,
                              void* d_out, int out_size) {
    const float* ea = (const float*)d_in[0];
    const float* eb = (const float*)d_in[1];
    const float* ec = (const float*)d_in[2];
    const float* wab = (const float*)d_in[3];
    const float* wac = (const float*)d_in[4];
    const float* wbc = (const float*)d_in[5];
    float* out = (float*)d_out;

    cudaFuncSetAttribute(gemm_s_mma, cudaFuncAttributeMaxDynamicSharedMemorySize, SMEM_S);
    cudaFuncSetAttribute(gemm_pv_mma, cudaFuncAttributeMaxDynamicSharedMemorySize, SMEM_PV);

    prep_kernel<<<dim3(512, 3), 256>>>(ea, eb, ec, wab, wac, wbc);
    gemm_s_mma<<<dim3(4, 4, 24), 256, SMEM_S>>>(nullptr);
    softmax_kernel<<<dim3(512, 3), 256>>>(nullptr);
    gemm_pv_mma<<<dim3(4, 4, 24), 256, SMEM_PV>>>(ea, eb, ec, out);
    beta_b2a_kernel<<<dim3(8, 3), 512>>>(ea, eb, ec);
    bcast_kernel<<<dim3(512, 8, 3), 128>>>(ea, eb, ec, out);
    copy_enc_kernel<<<dim3(512, 8, 3), 128>>>(ea, eb, ec, out);
}

// round 7
// speedup vs baseline: 3.1124x; 1.0018x over previous
#include <cuda_runtime.h>
#include <cstdint>

#define BATCH 8
#define L 512
#define D 512
#define OUTR 1536
#define OUTC 2560
#define NCHUNK 16
#define LDA 36     // [row][k] smem stride (floats)
#define LDBPV 136  // [k][n] smem stride for PV B (floats)

// Stage sizes (floats)
#define STAGE_S  (2 * 128 * LDA)              // 9216  (A 128x36 + B 128x36)
#define STAGE_PV (128 * LDA + 32 * LDBPV)     // 8960  (A 128x36 + B 32x136)
#define SMEM_S   (3 * STAGE_S * 4)            // 110592 B
#define SMEM_PV  (3 * STAGE_PV * 4)           // 107520 B

// Scratch (static device memory; allocation-free per harness rules)
__device__ float g_S[3][BATCH * L * L];     // S / P per pair (P stored tf32-rounded)
__device__ float g_Xw[3][BATCH * L * D];    // tf32(X * wM) per pair
__device__ float g_Yc[2][BATCH * L * D];    // tf32(enc_b), tf32(enc_c)
__device__ float g_r[3][2][BATCH * L];      // rX, rY per pair
__device__ float g_m[3][BATCH * L];         // row max per pair
__device__ float g_v[3][BATCH * D];         // b2a vector per pair

// ===========================================================================
// helpers
// ===========================================================================
__device__ __forceinline__ uint32_t f2tf(float f) {
    uint32_t r;
    asm("cvt.rna.tf32.f32 %0, %1;" : "=r"(r) : "f"(f));
    return r;
}
__device__ __forceinline__ float4 cvt4(float4 v) {
    v.x = __uint_as_float(f2tf(v.x));
    v.y = __uint_as_float(f2tf(v.y));
    v.z = __uint_as_float(f2tf(v.z));
    v.w = __uint_as_float(f2tf(v.w));
    return v;
}
__device__ __forceinline__ void mma8(float* c, const uint32_t* a, const uint32_t* b) {
    asm volatile(
        "mma.sync.aligned.m16n8k8.row.col.f32.tf32.tf32.f32 "
        "{%0,%1,%2,%3}, {%4,%5,%6,%7}, {%8,%9}, {%0,%1,%2,%3};"
        : "+f"(c[0]), "+f"(c[1]), "+f"(c[2]), "+f"(c[3])
        : "r"(a[0]), "r"(a[1]), "r"(a[2]), "r"(a[3]), "r"(b[0]), "r"(b[1]));
}
__device__ __forceinline__ void cp16(float* dst, const float* src) {
    uint32_t d = (uint32_t)__cvta_generic_to_shared(dst);
    asm volatile("cp.async.cg.shared.global [%0], [%1], 16;" :: "r"(d), "l"(src) : "memory");
}
__device__ __forceinline__ void cp_commit() {
    asm volatile("cp.async.commit_group;" ::: "memory");
}

// ===========================================================================
// prep: per encoder matrix, one pass: 2 row-dots + tf32-converted operand copies
// grid (512, 3), 256 threads (8 warps, 1 row/warp)
// ===========================================================================
__global__ void prep_kernel(const float* __restrict__ ea, const float* __restrict__ eb,
                            const float* __restrict__ ec,
                            const float* __restrict__ wab, const float* __restrict__ wac,
                            const float* __restrict__ wbc) {
    int mat = blockIdx.y;
    int row = blockIdx.x * 8 + (threadIdx.x >> 5);
    int lane = threadIdx.x & 31;

    const float *src, *w1, *w2, *sc1, *sc2;
    float *r1, *r2, *d1, *d2;
    if (mat == 0) {
        src = ea; w1 = wab; r1 = &g_r[0][0][0]; w2 = wac; r2 = &g_r[1][0][0];
        sc1 = wab + 1024; d1 = g_Xw[0]; sc2 = wac + 1024; d2 = g_Xw[1];
    } else if (mat == 1) {
        src = eb; w1 = wab + 512; r1 = &g_r[0][1][0]; w2 = wbc; r2 = &g_r[2][0][0];
        sc1 = wbc + 1024; d1 = g_Xw[2]; sc2 = nullptr; d2 = g_Yc[0];
    } else {
        src = ec; w1 = wac + 512; r1 = &g_r[1][1][0]; w2 = wbc + 512; r2 = &g_r[2][1][0];
        sc1 = nullptr; d1 = g_Yc[1]; sc2 = nullptr; d2 = nullptr;
    }

    const float* rp = src + (size_t)row * D;
    float4 x[4];
    float s1 = 0.f, s2 = 0.f;
#pragma unroll
    for (int t = 0; t < 4; t++) {
        int k = (t * 32 + lane) * 4;
        x[t] = *(const float4*)(rp + k);
        float4 a = *(const float4*)(w1 + k);
        s1 += x[t].x * a.x + x[t].y * a.y + x[t].z * a.z + x[t].w * a.w;
        float4 b = *(const float4*)(w2 + k);
        s2 += x[t].x * b.x + x[t].y * b.y + x[t].z * b.z + x[t].w * b.w;
    }
#pragma unroll
    for (int o = 16; o; o >>= 1) {
        s1 += __shfl_xor_sync(0xFFFFFFFFu, s1, o);
        s2 += __shfl_xor_sync(0xFFFFFFFFu, s2, o);
    }
    if (!lane) { r1[row] = s1; r2[row] = s2; }

#pragma unroll
    for (int t = 0; t < 4; t++) {
        int k = (t * 32 + lane) * 4;
        float4 v = x[t];
        if (sc1) {
            float4 s = *(const float4*)(sc1 + k);
            v.x *= s.x; v.y *= s.y; v.z *= s.z; v.w *= s.w;
        }
        *(float4*)(d1 + (size_t)row * D + k) = cvt4(v);
    }
    if (d2) {
#pragma unroll
        for (int t = 0; t < 4; t++) {
            int k = (t * 32 + lane) * 4;
            float4 v = x[t];
            if (sc2) {
                float4 s = *(const float4*)(sc2 + k);
                v.x *= s.x; v.y *= s.y; v.z *= s.z; v.w *= s.w;
            }
            *(float4*)(d2 + (size_t)row * D + k) = cvt4(v);
        }
    }
}

// ===========================================================================
// S GEMM (batched pairs): S = rX + rY + Xw @ Yc^T
// grid (4,4,24) z = pair*8 + b
// ===========================================================================
__global__ __launch_bounds__(256, 2)
void gemm_s_mma(const float* __restrict__ dummy) {
    extern __shared__ float sm[];
    int pair = blockIdx.z >> 3, b = blockIdx.z & 7;
    int yt = (pair == 0) ? 0 : 1;
    int i0 = blockIdx.y * 128, j0 = blockIdx.x * 128;
    const float* Ag = g_Xw[pair] + ((size_t)b * L + i0) * D;
    const float* Bg = g_Yc[yt] + ((size_t)b * L + j0) * D;
    int tid = threadIdx.x;

    int lane = tid & 31, w = tid >> 5;
    int ar = lane >> 2, ac = lane & 3;
    int mbase = (w & 1) * 64, nbase = (w >> 1) * 32;
    float acc[4][4][4] = {};

    auto issue = [&](int c, int st) {
        float* As = sm + st * STAGE_S;
        float* Bs = As + 128 * LDA;
        int k0 = c * 32;
#pragma unroll
        for (int it = 0; it < 4; it++) {
            int i = it * 256 + tid;
            int row = i >> 3, c4 = (i & 7) << 2;
            cp16(As + row * LDA + c4, Ag + (size_t)row * D + k0 + c4);
            cp16(Bs + row * LDA + c4, Bg + (size_t)row * D + k0 + c4);
        }
        cp_commit();
    };

    issue(0, 0);
    issue(1, 1);
    int st_c = 0, st_n = 2;
    for (int c = 0; c < NCHUNK; c++) {
        if (c < NCHUNK - 1) asm volatile("cp.async.wait_group 1;" ::: "memory");
        else                asm volatile("cp.async.wait_group 0;" ::: "memory");
        __syncthreads();
        if (c + 2 < NCHUNK) issue(c + 2, st_n);
        const float* a_s = sm + st_c * STAGE_S;
        const float* b_s = a_s + 128 * LDA;
#pragma unroll
        for (int ks = 0; ks < 4; ks++) {
            int k0 = ks * 8;
            uint32_t af[4][4], bf[4][2];
#pragma unroll
            for (int mt = 0; mt < 4; mt++) {
                const float* p = a_s + (mbase + mt * 16 + ar) * LDA + k0 + ac;
                af[mt][0] = __float_as_uint(p[0]);
                af[mt][1] = __float_as_uint(p[8 * LDA]);
                af[mt][2] = __float_as_uint(p[4]);
                af[mt][3] = __float_as_uint(p[8 * LDA + 4]);
            }
#pragma unroll
            for (int nt = 0; nt < 4; nt++) {
                const float* p = b_s + (nbase + nt * 8 + ar) * LDA + k0 + ac;
                bf[nt][0] = __float_as_uint(p[0]);
                bf[nt][1] = __float_as_uint(p[4]);
            }
#pragma unroll
            for (int mt = 0; mt < 4; mt++)
#pragma unroll
                for (int nt = 0; nt < 4; nt++) mma8(acc[mt][nt], af[mt], bf[nt]);
        }
        st_c = (st_c == 2) ? 0 : st_c + 1;
        st_n = (st_n == 2) ? 0 : st_n + 1;
    }

    const float* rx = g_r[pair][0] + b * L + i0;
    const float* ry = g_r[pair][1] + b * L + j0;
    float* Sp = g_S[pair] + ((size_t)b * L + i0) * L + j0;
#pragma unroll
    for (int mt = 0; mt < 4; mt++) {
        int r = mbase + mt * 16 + ar;
        float rx0 = rx[r], rx1 = rx[r + 8];
#pragma unroll
        for (int nt = 0; nt < 4; nt++) {
            int cI = nbase + nt * 8 + ac * 2;
            float ry0 = ry[cI], ry1 = ry[cI + 1];
            float2 v0 = make_float2(acc[mt][nt][0] + rx0 + ry0, acc[mt][nt][1] + rx0 + ry1);
            float2 v1 = make_float2(acc[mt][nt][2] + rx1 + ry0, acc[mt][nt][3] + rx1 + ry1);
            *(float2*)(Sp + (size_t)r * L + cI) = v0;
            *(float2*)(Sp + (size_t)(r + 8) * L + cI) = v1;
        }
    }
}

// ===========================================================================
// PV GEMM (batched pairs): O = P @ Yc; fused concat writes (raw + E*O)
// ===========================================================================
__constant__ int c_secRowA[3] = {0, 0, 512};
__constant__ int c_offRawA[3] = {512, 1024, 1024};
__constant__ int c_offProdA[3] = {1536, 2048, 2048};

__global__ __launch_bounds__(256, 2)
void gemm_pv_mma(const float* __restrict__ ea, const float* __restrict__ eb,
                 const float* __restrict__ ec, float* __restrict__ out) {
    extern __shared__ float sm[];
    int pair = blockIdx.z >> 3, b = blockIdx.z & 7;
    int yt = (pair == 0) ? 0 : 1;
    const float* E = (pair == 2) ? eb : ea;
    int secRow = c_secRowA[pair], offRaw = c_offRawA[pair], offProd = c_offProdA[pair];
    int i0 = blockIdx.y * 128, d0 = blockIdx.x * 128;
    const float* Ag = g_S[pair] + ((size_t)b * L + i0) * L;
    const float* Bg = g_Yc[yt] + (size_t)b * L * D + d0;
    int tid = threadIdx.x;

    int lane = tid & 31, w = tid >> 5;
    int ar = lane >> 2, ac = lane & 3;
    int mbase = (w & 1) * 64, nbase = (w >> 1) * 32;
    float acc[4][4][4] = {};

    auto issue = [&](int c, int st) {
        float* As = sm + st * STAGE_PV;
        float* Bs = As + 128 * LDA;
        int k0 = c * 32;
#pragma unroll
        for (int it = 0; it < 4; it++) {
            int i = it * 256 + tid;
            int arow = i >> 3, ac4 = (i & 7) << 2;
            cp16(As + arow * LDA + ac4, Ag + (size_t)arow * L + k0 + ac4);
            int brow = i >> 5, bc4 = (i & 31) << 2;
            cp16(Bs + brow * LDBPV + bc4, Bg + (size_t)(k0 + brow) * D + bc4);
        }
        cp_commit();
    };

    issue(0, 0);
    issue(1, 1);
    int st_c = 0, st_n = 2;
    for (int c = 0; c < NCHUNK; c++) {
        if (c < NCHUNK - 1) asm volatile("cp.async.wait_group 1;" ::: "memory");
        else                asm volatile("cp.async.wait_group 0;" ::: "memory");
        __syncthreads();
        if (c + 2 < NCHUNK) issue(c + 2, st_n);
        const float* a_s = sm + st_c * STAGE_PV;
        const float* b_s = a_s + 128 * LDA;
#pragma unroll
        for (int ks = 0; ks < 4; ks++) {
            int k0 = ks * 8;
            uint32_t af[4][4], bf[4][2];
#pragma unroll
            for (int mt = 0; mt < 4; mt++) {
                const float* p = a_s + (mbase + mt * 16 + ar) * LDA + k0 + ac;
                af[mt][0] = __float_as_uint(p[0]);
                af[mt][1] = __float_as_uint(p[8 * LDA]);
                af[mt][2] = __float_as_uint(p[4]);
                af[mt][3] = __float_as_uint(p[8 * LDA + 4]);
            }
#pragma unroll
            for (int nt = 0; nt < 4; nt++) {
                const float* p = b_s + (k0 + ac) * LDBPV + nbase + nt * 8 + ar;
                bf[nt][0] = __float_as_uint(p[0]);
                bf[nt][1] = __float_as_uint(p[4 * LDBPV]);
            }
#pragma unroll
            for (int mt = 0; mt < 4; mt++)
#pragma unroll
                for (int nt = 0; nt < 4; nt++) mma8(acc[mt][nt], af[mt], bf[nt]);
        }
        st_c = (st_c == 2) ? 0 : st_c + 1;
        st_n = (st_n == 2) ? 0 : st_n + 1;
    }

#pragma unroll
    for (int mt = 0; mt < 4; mt++) {
        int r = mbase + mt * 16 + ar;
        int i = i0 + r;
        const float* e0p = E + ((size_t)b * L + i) * D + d0;
        float* o0p = out + ((size_t)b * OUTR + secRow + i) * OUTC;
#pragma unroll
        for (int nt = 0; nt < 4; nt++) {
            int cI = nbase + nt * 8 + ac * 2;
            float2 e0 = *(const float2*)(e0p + cI);
            float2 e1 = *(const float2*)(e0p + 8 * D + cI);
            float2 v0 = make_float2(acc[mt][nt][0], acc[mt][nt][1]);
            float2 v1 = make_float2(acc[mt][nt][2], acc[mt][nt][3]);
            *(float2*)(o0p + offRaw + d0 + cI) = v0;
            *(float2*)(o0p + 8 * OUTC + offRaw + d0 + cI) = v1;
            *(float2*)(o0p + offProd + d0 + cI) = make_float2(v0.x * e0.x, v0.y * e0.y);
            *(float2*)(o0p + 8 * OUTC + offProd + d0 + cI) = make_float2(v1.x * e1.x, v1.y * e1.y);
        }
    }
}

// ===========================================================================
// softmax (batched): in-place row softmax of S, P stored tf32-rounded; rowmax out
// grid (512, 3)
// ===========================================================================
__global__ void softmax_kernel(const float* __restrict__ dummy) {
    int pair = blockIdx.y;
    int row = blockIdx.x * 8 + (threadIdx.x >> 5);
    int lane = threadIdx.x & 31;
    float* r = g_S[pair] + (size_t)row * L;
    float4 v[4];
    float mx = -1e30f;
#pragma unroll
    for (int t = 0; t < 4; t++) {
        v[t] = ((float4*)r)[t * 32 + lane];
        mx = fmaxf(mx, fmaxf(fmaxf(v[t].x, v[t].y), fmaxf(v[t].z, v[t].w)));
    }
#pragma unroll
    for (int o = 16; o; o >>= 1) mx = fmaxf(mx, __shfl_xor_sync(0xFFFFFFFFu, mx, o));
    float s = 0.f;
#pragma unroll
    for (int t = 0; t < 4; t++) {
        v[t].x = __expf(v[t].x - mx);
        v[t].y = __expf(v[t].y - mx);
        v[t].z = __expf(v[t].z - mx);
        v[t].w = __expf(v[t].w - mx);
        s += v[t].x + v[t].y + v[t].z + v[t].w;
    }
#pragma unroll
    for (int o = 16; o; o >>= 1) s += __shfl_xor_sync(0xFFFFFFFFu, s, o);
    float inv = 1.f / s;
#pragma unroll
    for (int t = 0; t < 4; t++) {
        v[t].x *= inv; v[t].y *= inv; v[t].z *= inv; v[t].w *= inv;
        ((float4*)r)[t * 32 + lane] = cvt4(v[t]);
    }
    if (!lane) g_m[pair][row] = mx;
}

// ===========================================================================
// beta (batched): beta = softmax_i(m); v = sum_i beta_i * X[b,i,:]. grid (8,3)
// ===========================================================================
__global__ __launch_bounds__(512)
void beta_b2a_kernel(const float* __restrict__ ea, const float* __restrict__ eb,
                     const float* __restrict__ ec) {
    int b = blockIdx.x, pair = blockIdx.y, t = threadIdx.x;
    const float* X = (pair == 2) ? eb : ea;
    int lane = t & 31, wid = t >> 5;
    __shared__ float sb[512];
    __shared__ float redm[16];
    __shared__ float reds[16];
    __shared__ float bc[2];
    float mv = g_m[pair][b * L + t];
    float v = mv;
#pragma unroll
    for (int o = 16; o; o >>= 1) v = fmaxf(v, __shfl_xor_sync(0xFFFFFFFFu, v, o));
    if (!lane) redm[wid] = v;
    __syncthreads();
    if (t == 0) {
        float m2 = redm[0];
        for (int i = 1; i < 16; i++) m2 = fmaxf(m2, redm[i]);
        bc[0] = m2;
    }
    __syncthreads();
    float mx = bc[0];
    float e = __expf(mv - mx);
    v = e;
#pragma unroll
    for (int o = 16; o; o >>= 1) v += __shfl_xor_sync(0xFFFFFFFFu, v, o);
    if (!lane) reds[wid] = v;
    __syncthreads();
    if (t == 0) {
        float s = 0.f;
        for (int i = 0; i < 16; i++) s += reds[i];
        bc[1] = s;
    }
    __syncthreads();
    sb[t] = e / bc[1];
    __syncthreads();
    const float* Xb = X + (size_t)b * L * D;
    float acc = 0.f;
#pragma unroll 8
    for (int i = 0; i < L; i++) acc += sb[i] * Xb[(size_t)i * D + t];
    g_v[pair][b * D + t] = acc;
}

// ===========================================================================
// tail: fused enc copy + vector broadcast (raw + E*vec). grid (512, 8, 3)
// section 0 (a): copy only. section 1 (b): copy + pair0 vec (@512/1536).
// section 2 (c): copy + pair1 vec (@512/1536) + pair2 vec (@1024/2048).
// Writes identical addresses to R5's copy_enc_kernel + bcast_kernel.
// ===========================================================================
__global__ void tail_kernel(const float* __restrict__ ea, const float* __restrict__ eb,
                            const float* __restrict__ ec, float* __restrict__ out) {
    int s = blockIdx.z, b = blockIdx.y, r = blockIdx.x;
    const float* E = (s == 0) ? ea : (s == 1) ? eb : ec;
    int t = threadIdx.x;
    float4 e = ((const float4*)(E + ((size_t)b * L + r) * D))[t];
    float* row = out + ((size_t)b * OUTR + s * 512 + r) * OUTC;
    ((float4*)row)[t] = e;
    if (s == 1) {
        float4 vv = ((const float4*)(&g_v[0][b * D]))[t];
        ((float4*)(row + 512))[t] = vv;
        ((float4*)(row + 1536))[t] = make_float4(vv.x * e.x, vv.y * e.y, vv.z * e.z, vv.w * e.w);
    } else if (s == 2) {
        float4 v1 = ((const float4*)(&g_v[1][b * D]))[t];
        ((float4*)(row + 512))[t] = v1;
        ((float4*)(row + 1536))[t] = make_float4(v1.x * e.x, v1.y * e.y, v1.z * e.z, v1.w * e.w);
        float4 v2 = ((const float4*)(&g_v[2][b * D]))[t];
        ((float4*)(row + 1024))[t] = v2;
        ((float4*)(row + 2048))[t] = make_float4(v2.x * e.x, v2.y * e.y, v2.z * e.z, v2.w * e.w);
    }
}

// ===========================================================================
extern "C" void kernel_launch(void* const* d_in, const int* in_sizes, int n_in,
                              void* d_out, int out_size) {
    const float* ea = (const float*)d_in[0];
    const float* eb = (const float*)d_in[1];
    const float* ec = (const float*)d_in[2];
    const float* wab = (const float*)d_in[3];
    const float* wac = (const float*)d_in[4];
    const float* wbc = (const float*)d_in[5];
    float* out = (float*)d_out;

    cudaFuncSetAttribute(gemm_s_mma, cudaFuncAttributeMaxDynamicSharedMemorySize, SMEM_S);
    cudaFuncSetAttribute(gemm_pv_mma, cudaFuncAttributeMaxDynamicSharedMemorySize, SMEM_PV);

    prep_kernel<<<dim3(512, 3), 256>>>(ea, eb, ec, wab, wac, wbc);
    gemm_s_mma<<<dim3(4, 4, 24), 256, SMEM_S>>>(nullptr);
    softmax_kernel<<<dim3(512, 3), 256>>>(nullptr);
    gemm_pv_mma<<<dim3(4, 4, 24), 256, SMEM_PV>>>(ea, eb, ec, out);
    beta_b2a_kernel<<<dim3(8, 3), 512>>>(ea, eb, ec);
    tail_kernel<<<dim3(512, 8, 3), 128>>>(ea, eb, ec, out);
}

// round 8
// speedup vs baseline: 3.3449x; 1.0747x over previous
#include <cuda_runtime.h>
#include <cstdint>

#define BATCH 8
#define L 512
#define D 512
#define OUTR 1536
#define OUTC 2560
#define NCHUNK 16
#define LDA 40     // [row][k] smem stride (floats) — conflict-free float2 frags
#define LDBPV 136  // [k][n] smem stride for PV B (floats)

// Stage sizes (floats)
#define STAGE_S  (2 * 128 * LDA)              // 10240 (A 128x40 + B 128x40)
#define STAGE_PV (128 * LDA + 32 * LDBPV)     // 9472  (A 128x40 + B 32x136)
#define SMEM_S   (2 * STAGE_S * 4)            // 81920 B (2-stage)
#define SMEM_PV  (2 * STAGE_PV * 4)           // 75776 B (2-stage)

// Scratch (static device memory; allocation-free per harness rules)
__device__ float g_S[3][BATCH * L * L];     // S natural; P stored tf32 + k-permuted
__device__ float g_Xw[3][BATCH * L * D];    // tf32(X * wM), k-permuted
__device__ float g_Yc[2][BATCH * L * D];    // tf32(enc_b), tf32(enc_c), natural
__device__ float g_r[3][2][BATCH * L];      // rX, rY per pair
__device__ float g_m[3][BATCH * L];         // row max per pair
__device__ float g_v[3][BATCH * D];         // b2a vector per pair

// ===========================================================================
// helpers
// ===========================================================================
__device__ __forceinline__ uint32_t f2tf(float f) {
    uint32_t r;
    asm("cvt.rna.tf32.f32 %0, %1;" : "=r"(r) : "f"(f));
    return r;
}
__device__ __forceinline__ float4 cvt4(float4 v) {
    v.x = __uint_as_float(f2tf(v.x));
    v.y = __uint_as_float(f2tf(v.y));
    v.z = __uint_as_float(f2tf(v.z));
    v.w = __uint_as_float(f2tf(v.w));
    return v;
}
// Within-8-group k permutation: positions [0..7] hold cols [0,4,1,5,2,6,3,7].
// Adjacent lanes (even: cols 0-3 of group, odd: cols 4-7) exchange via shfl.
__device__ __forceinline__ float4 perm8(float4 v) {
    float4 q;
    q.x = __shfl_xor_sync(0xFFFFFFFFu, v.x, 1);
    q.y = __shfl_xor_sync(0xFFFFFFFFu, v.y, 1);
    q.z = __shfl_xor_sync(0xFFFFFFFFu, v.z, 1);
    q.w = __shfl_xor_sync(0xFFFFFFFFu, v.w, 1);
    return (threadIdx.x & 1) ? make_float4(q.z, v.z, q.w, v.w)
                             : make_float4(v.x, q.x, v.y, q.y);
}
__device__ __forceinline__ void mma8(float* c, const uint32_t* a, const uint32_t* b) {
    asm volatile(
        "mma.sync.aligned.m16n8k8.row.col.f32.tf32.tf32.f32 "
        "{%0,%1,%2,%3}, {%4,%5,%6,%7}, {%8,%9}, {%0,%1,%2,%3};"
        : "+f"(c[0]), "+f"(c[1]), "+f"(c[2]), "+f"(c[3])
        : "r"(a[0]), "r"(a[1]), "r"(a[2]), "r"(a[3]), "r"(b[0]), "r"(b[1]));
}
__device__ __forceinline__ void cp16(float* dst, const float* src) {
    uint32_t d = (uint32_t)__cvta_generic_to_shared(dst);
    asm volatile("cp.async.cg.shared.global [%0], [%1], 16;" :: "r"(d), "l"(src) : "memory");
}
__device__ __forceinline__ void cp_commit() {
    asm volatile("cp.async.commit_group;" ::: "memory");
}

// ===========================================================================
// prep: per encoder matrix: 2 row-dots + tf32 operand copies.
// Destinations feeding A-operands (g_Xw) get wM scale (where applicable),
// tf32 rounding, then k-permutation. g_Yc copies: tf32 only, natural order.
// grid (512, 3), 256 threads
// ===========================================================================
__global__ void prep_kernel(const float* __restrict__ ea, const float* __restrict__ eb,
                            const float* __restrict__ ec,
                            const float* __restrict__ wab, const float* __restrict__ wac,
                            const float* __restrict__ wbc) {
    int mat = blockIdx.y;
    int row = blockIdx.x * 8 + (threadIdx.x >> 5);
    int lane = threadIdx.x & 31;

    const float *src, *w1, *w2, *sc1, *sc2;
    float *r1, *r2, *d1, *d2;
    int p1, p2;
    if (mat == 0) {
        src = ea; w1 = wab; r1 = &g_r[0][0][0]; w2 = wac; r2 = &g_r[1][0][0];
        sc1 = wab + 1024; d1 = g_Xw[0]; p1 = 1;
        sc2 = wac + 1024; d2 = g_Xw[1]; p2 = 1;
    } else if (mat == 1) {
        src = eb; w1 = wab + 512; r1 = &g_r[0][1][0]; w2 = wbc; r2 = &g_r[2][0][0];
        sc1 = wbc + 1024; d1 = g_Xw[2]; p1 = 1;
        sc2 = nullptr; d2 = g_Yc[0]; p2 = 0;
    } else {
        src = ec; w1 = wac + 512; r1 = &g_r[1][1][0]; w2 = wbc + 512; r2 = &g_r[2][1][0];
        sc1 = nullptr; d1 = g_Yc[1]; p1 = 0;
        sc2 = nullptr; d2 = nullptr; p2 = 0;
    }

    const float* rp = src + (size_t)row * D;
    float4 x[4];
    float s1 = 0.f, s2 = 0.f;
#pragma unroll
    for (int t = 0; t < 4; t++) {
        int k = (t * 32 + lane) * 4;
        x[t] = *(const float4*)(rp + k);
        float4 a = *(const float4*)(w1 + k);
        s1 += x[t].x * a.x + x[t].y * a.y + x[t].z * a.z + x[t].w * a.w;
        float4 b = *(const float4*)(w2 + k);
        s2 += x[t].x * b.x + x[t].y * b.y + x[t].z * b.z + x[t].w * b.w;
    }
#pragma unroll
    for (int o = 16; o; o >>= 1) {
        s1 += __shfl_xor_sync(0xFFFFFFFFu, s1, o);
        s2 += __shfl_xor_sync(0xFFFFFFFFu, s2, o);
    }
    if (!lane) { r1[row] = s1; r2[row] = s2; }

#pragma unroll
    for (int t = 0; t < 4; t++) {
        int k = (t * 32 + lane) * 4;
        float4 v = x[t];
        if (sc1) {                               // scale FIRST (R6 bug: was dropped)
            float4 s = *(const float4*)(sc1 + k);
            v.x *= s.x; v.y *= s.y; v.z *= s.z; v.w *= s.w;
        }
        v = cvt4(v);
        if (p1) v = perm8(v);
        *(float4*)(d1 + (size_t)row * D + k) = v;
    }
    if (d2) {
#pragma unroll
        for (int t = 0; t < 4; t++) {
            int k = (t * 32 + lane) * 4;
            float4 v = x[t];
            if (sc2) {                           // scale FIRST (the fix)
                float4 s = *(const float4*)(sc2 + k);
                v.x *= s.x; v.y *= s.y; v.z *= s.z; v.w *= s.w;
            }
            v = cvt4(v);
            if (p2) v = perm8(v);
            *(float4*)(d2 + (size_t)row * D + k) = v;
        }
    }
}

// ===========================================================================
// S GEMM (batched): S = rX + rY + Xw @ Yc^T.  grid (4,4,24) z = pair*8 + b
// A smem [m][k-perm] 128x40 (float2 frags); B smem [n][k] 128x40 (scalar)
// ===========================================================================
__global__ __launch_bounds__(256, 2)
void gemm_s_mma(const float* __restrict__ dummy) {
    extern __shared__ float sm[];
    int pair = blockIdx.z >> 3, b = blockIdx.z & 7;
    int yt = (pair == 0) ? 0 : 1;
    int i0 = blockIdx.y * 128, j0 = blockIdx.x * 128;
    const float* Ag = g_Xw[pair] + ((size_t)b * L + i0) * D;
    const float* Bg = g_Yc[yt] + ((size_t)b * L + j0) * D;
    int tid = threadIdx.x;

    int lane = tid & 31, w = tid >> 5;
    int ar = lane >> 2, ac = lane & 3;
    int mbase = (w & 1) * 64, nbase = (w >> 1) * 32;
    float acc[4][4][4] = {};

    auto issue = [&](int c, int st) {
        float* As = sm + st * STAGE_S;
        float* Bs = As + 128 * LDA;
        int k0 = c * 32;
#pragma unroll
        for (int it = 0; it < 4; it++) {
            int i = it * 256 + tid;
            int row = i >> 3, c4 = (i & 7) << 2;
            cp16(As + row * LDA + c4, Ag + (size_t)row * D + k0 + c4);
            cp16(Bs + row * LDA + c4, Bg + (size_t)row * D + k0 + c4);
        }
        cp_commit();
    };

    issue(0, 0);
    for (int c = 0; c < NCHUNK; c++) {
        if (c + 1 < NCHUNK) {
            issue(c + 1, (c + 1) & 1);
            asm volatile("cp.async.wait_group 1;" ::: "memory");
        } else {
            asm volatile("cp.async.wait_group 0;" ::: "memory");
        }
        __syncthreads();
        const float* a_s = sm + (c & 1) * STAGE_S;
        const float* b_s = a_s + 128 * LDA;
#pragma unroll
        for (int ks = 0; ks < 4; ks++) {
            uint32_t af[4][4], bf[4][2];
#pragma unroll
            for (int mt = 0; mt < 4; mt++) {
                const float* p = a_s + (mbase + mt * 16 + ar) * LDA + ks * 8 + ac * 2;
                float2 a0 = *(const float2*)p;                // (r, ac), (r, ac+4)
                float2 a1 = *(const float2*)(p + 8 * LDA);    // (r+8, ac), (r+8, ac+4)
                af[mt][0] = __float_as_uint(a0.x);
                af[mt][1] = __float_as_uint(a1.x);
                af[mt][2] = __float_as_uint(a0.y);
                af[mt][3] = __float_as_uint(a1.y);
            }
#pragma unroll
            for (int nt = 0; nt < 4; nt++) {
                const float* q = b_s + (nbase + nt * 8 + ar) * LDA + ks * 8 + ac;
                bf[nt][0] = __float_as_uint(q[0]);
                bf[nt][1] = __float_as_uint(q[4]);
            }
#pragma unroll
            for (int mt = 0; mt < 4; mt++)
#pragma unroll
                for (int nt = 0; nt < 4; nt++) mma8(acc[mt][nt], af[mt], bf[nt]);
        }
        __syncthreads();
    }

    const float* rx = g_r[pair][0] + b * L + i0;
    const float* ry = g_r[pair][1] + b * L + j0;
    float* Sp = g_S[pair] + ((size_t)b * L + i0) * L + j0;
#pragma unroll
    for (int mt = 0; mt < 4; mt++) {
        int r = mbase + mt * 16 + ar;
        float rx0 = rx[r], rx1 = rx[r + 8];
#pragma unroll
        for (int nt = 0; nt < 4; nt++) {
            int cI = nbase + nt * 8 + ac * 2;
            float ry0 = ry[cI], ry1 = ry[cI + 1];
            float2 v0 = make_float2(acc[mt][nt][0] + rx0 + ry0, acc[mt][nt][1] + rx0 + ry1);
            float2 v1 = make_float2(acc[mt][nt][2] + rx1 + ry0, acc[mt][nt][3] + rx1 + ry1);
            *(float2*)(Sp + (size_t)r * L + cI) = v0;
            *(float2*)(Sp + (size_t)(r + 8) * L + cI) = v1;
        }
    }
}

// ===========================================================================
// PV GEMM (batched): O = P @ Yc; fused concat writes.  grid (4,4,24)
// A smem [i][j-perm] 128x40 (float2 frags); B smem [j][d] 32x136 (scalar)
// ===========================================================================
__constant__ int c_secRowA[3] = {0, 0, 512};
__constant__ int c_offRawA[3] = {512, 1024, 1024};
__constant__ int c_offProdA[3] = {1536, 2048, 2048};

__global__ __launch_bounds__(256, 2)
void gemm_pv_mma(const float* __restrict__ ea, const float* __restrict__ eb,
                 const float* __restrict__ ec, float* __restrict__ out) {
    extern __shared__ float sm[];
    int pair = blockIdx.z >> 3, b = blockIdx.z & 7;
    int yt = (pair == 0) ? 0 : 1;
    const float* E = (pair == 2) ? eb : ea;
    int secRow = c_secRowA[pair], offRaw = c_offRawA[pair], offProd = c_offProdA[pair];
    int i0 = blockIdx.y * 128, d0 = blockIdx.x * 128;
    const float* Ag = g_S[pair] + ((size_t)b * L + i0) * L;
    const float* Bg = g_Yc[yt] + (size_t)b * L * D + d0;
    int tid = threadIdx.x;

    int lane = tid & 31, w = tid >> 5;
    int ar = lane >> 2, ac = lane & 3;
    int mbase = (w & 1) * 64, nbase = (w >> 1) * 32;
    float acc[4][4][4] = {};

    auto issue = [&](int c, int st) {
        float* As = sm + st * STAGE_PV;
        float* Bs = As + 128 * LDA;
        int k0 = c * 32;
#pragma unroll
        for (int it = 0; it < 4; it++) {
            int i = it * 256 + tid;
            int arow = i >> 3, ac4 = (i & 7) << 2;
            cp16(As + arow * LDA + ac4, Ag + (size_t)arow * L + k0 + ac4);
            int brow = i >> 5, bc4 = (i & 31) << 2;
            cp16(Bs + brow * LDBPV + bc4, Bg + (size_t)(k0 + brow) * D + bc4);
        }
        cp_commit();
    };

    issue(0, 0);
    for (int c = 0; c < NCHUNK; c++) {
        if (c + 1 < NCHUNK) {
            issue(c + 1, (c + 1) & 1);
            asm volatile("cp.async.wait_group 1;" ::: "memory");
        } else {
            asm volatile("cp.async.wait_group 0;" ::: "memory");
        }
        __syncthreads();
        const float* a_s = sm + (c & 1) * STAGE_PV;
        const float* b_s = a_s + 128 * LDA;
#pragma unroll
        for (int ks = 0; ks < 4; ks++) {
            uint32_t af[4][4], bf[4][2];
#pragma unroll
            for (int mt = 0; mt < 4; mt++) {
                const float* p = a_s + (mbase + mt * 16 + ar) * LDA + ks * 8 + ac * 2;
                float2 a0 = *(const float2*)p;
                float2 a1 = *(const float2*)(p + 8 * LDA);
                af[mt][0] = __float_as_uint(a0.x);
                af[mt][1] = __float_as_uint(a1.x);
                af[mt][2] = __float_as_uint(a0.y);
                af[mt][3] = __float_as_uint(a1.y);
            }
#pragma unroll
            for (int nt = 0; nt < 4; nt++) {
                const float* q = b_s + (ks * 8 + ac) * LDBPV + nbase + nt * 8 + ar;
                bf[nt][0] = __float_as_uint(q[0]);
                bf[nt][1] = __float_as_uint(q[4 * LDBPV]);
            }
#pragma unroll
            for (int mt = 0; mt < 4; mt++)
#pragma unroll
                for (int nt = 0; nt < 4; nt++) mma8(acc[mt][nt], af[mt], bf[nt]);
        }
        __syncthreads();
    }

#pragma unroll
    for (int mt = 0; mt < 4; mt++) {
        int r = mbase + mt * 16 + ar;
        int i = i0 + r;
        const float* e0p = E + ((size_t)b * L + i) * D + d0;
        float* o0p = out + ((size_t)b * OUTR + secRow + i) * OUTC;
#pragma unroll
        for (int nt = 0; nt < 4; nt++) {
            int cI = nbase + nt * 8 + ac * 2;
            float2 e0 = *(const float2*)(e0p + cI);
            float2 e1 = *(const float2*)(e0p + 8 * D + cI);
            float2 v0 = make_float2(acc[mt][nt][0], acc[mt][nt][1]);
            float2 v1 = make_float2(acc[mt][nt][2], acc[mt][nt][3]);
            *(float2*)(o0p + offRaw + d0 + cI) = v0;
            *(float2*)(o0p + 8 * OUTC + offRaw + d0 + cI) = v1;
            *(float2*)(o0p + offProd + d0 + cI) = make_float2(v0.x * e0.x, v0.y * e0.y);
            *(float2*)(o0p + 8 * OUTC + offProd + d0 + cI) = make_float2(v1.x * e1.x, v1.y * e1.y);
        }
    }
}

// ===========================================================================
// softmax (batched): in-place row softmax; P stored tf32 + k-permuted. grid (512,3)
// ===========================================================================
__global__ void softmax_kernel(const float* __restrict__ dummy) {
    int pair = blockIdx.y;
    int row = blockIdx.x * 8 + (threadIdx.x >> 5);
    int lane = threadIdx.x & 31;
    float* r = g_S[pair] + (size_t)row * L;
    float4 v[4];
    float mx = -1e30f;
#pragma unroll
    for (int t = 0; t < 4; t++) {
        v[t] = ((float4*)r)[t * 32 + lane];
        mx = fmaxf(mx, fmaxf(fmaxf(v[t].x, v[t].y), fmaxf(v[t].z, v[t].w)));
    }
#pragma unroll
    for (int o = 16; o; o >>= 1) mx = fmaxf(mx, __shfl_xor_sync(0xFFFFFFFFu, mx, o));
    float s = 0.f;
#pragma unroll
    for (int t = 0; t < 4; t++) {
        v[t].x = __expf(v[t].x - mx);
        v[t].y = __expf(v[t].y - mx);
        v[t].z = __expf(v[t].z - mx);
        v[t].w = __expf(v[t].w - mx);
        s += v[t].x + v[t].y + v[t].z + v[t].w;
    }
#pragma unroll
    for (int o = 16; o; o >>= 1) s += __shfl_xor_sync(0xFFFFFFFFu, s, o);
    float inv = 1.f / s;
#pragma unroll
    for (int t = 0; t < 4; t++) {
        v[t].x *= inv; v[t].y *= inv; v[t].z *= inv; v[t].w *= inv;
        ((float4*)r)[t * 32 + lane] = perm8(cvt4(v[t]));
    }
    if (!lane) g_m[pair][row] = mx;
}

// ===========================================================================
// beta (batched): beta = softmax_i(m); v = sum_i beta_i * X[b,i,:]. grid (8,3)
// ===========================================================================
__global__ __launch_bounds__(512)
void beta_b2a_kernel(const float* __restrict__ ea, const float* __restrict__ eb,
                     const float* __restrict__ ec) {
    int b = blockIdx.x, pair = blockIdx.y, t = threadIdx.x;
    const float* X = (pair == 2) ? eb : ea;
    int lane = t & 31, wid = t >> 5;
    __shared__ float sb[512];
    __shared__ float redm[16];
    __shared__ float reds[16];
    __shared__ float bc[2];
    float mv = g_m[pair][b * L + t];
    float v = mv;
#pragma unroll
    for (int o = 16; o; o >>= 1) v = fmaxf(v, __shfl_xor_sync(0xFFFFFFFFu, v, o));
    if (!lane) redm[wid] = v;
    __syncthreads();
    if (t == 0) {
        float m2 = redm[0];
        for (int i = 1; i < 16; i++) m2 = fmaxf(m2, redm[i]);
        bc[0] = m2;
    }
    __syncthreads();
    float mx = bc[0];
    float e = __expf(mv - mx);
    v = e;
#pragma unroll
    for (int o = 16; o; o >>= 1) v += __shfl_xor_sync(0xFFFFFFFFu, v, o);
    if (!lane) reds[wid] = v;
    __syncthreads();
    if (t == 0) {
        float s = 0.f;
        for (int i = 0; i < 16; i++) s += reds[i];
        bc[1] = s;
    }
    __syncthreads();
    sb[t] = e / bc[1];
    __syncthreads();
    const float* Xb = X + (size_t)b * L * D;
    float acc = 0.f;
#pragma unroll 8
    for (int i = 0; i < L; i++) acc += sb[i] * Xb[(size_t)i * D + t];
    g_v[pair][b * D + t] = acc;
}

// ===========================================================================
// tail: fused enc copy + vector broadcast (raw + E*vec). grid (512, 8, 3)
// ===========================================================================
__global__ void tail_kernel(const float* __restrict__ ea, const float* __restrict__ eb,
                            const float* __restrict__ ec, float* __restrict__ out) {
    int s = blockIdx.z, b = blockIdx.y, r = blockIdx.x;
    const float* E = (s == 0) ? ea : (s == 1) ? eb : ec;
    int t = threadIdx.x;
    float4 e = ((const float4*)(E + ((size_t)b * L + r) * D))[t];
    float* row = out + ((size_t)b * OUTR + s * 512 + r) * OUTC;
    ((float4*)row)[t] = e;
    if (s == 1) {
        float4 vv = ((const float4*)(&g_v[0][b * D]))[t];
        ((float4*)(row + 512))[t] = vv;
        ((float4*)(row + 1536))[t] = make_float4(vv.x * e.x, vv.y * e.y, vv.z * e.z, vv.w * e.w);
    } else if (s == 2) {
        float4 v1 = ((const float4*)(&g_v[1][b * D]))[t];
        ((float4*)(row + 512))[t] = v1;
        ((float4*)(row + 1536))[t] = make_float4(v1.x * e.x, v1.y * e.y, v1.z * e.z, v1.w * e.w);
        float4 v2 = ((const float4*)(&g_v[2][b * D]))[t];
        ((float4*)(row + 1024))[t] = v2;
        ((float4*)(row + 2048))[t] = make_float4(v2.x * e.x, v2.y * e.y, v2.z * e.z, v2.w * e.w);
    }
}

// ===========================================================================
extern "C" void kernel_launch(void* const* d_in, const int* in_sizes, int n_in,
                              void* d_out, int out_size) {
    const float* ea = (const float*)d_in[0];
    const float* eb = (const float*)d_in[1];
    const float* ec = (const float*)d_in[2];
    const float* wab = (const float*)d_in[3];
    const float* wac = (const float*)d_in[4];
    const float* wbc = (const float*)d_in[5];
    float* out = (float*)d_out;

    cudaFuncSetAttribute(gemm_s_mma, cudaFuncAttributeMaxDynamicSharedMemorySize, SMEM_S);
    cudaFuncSetAttribute(gemm_pv_mma, cudaFuncAttributeMaxDynamicSharedMemorySize, SMEM_PV);

    prep_kernel<<<dim3(512, 3), 256>>>(ea, eb, ec, wab, wac, wbc);
    gemm_s_mma<<<dim3(4, 4, 24), 256, SMEM_S>>>(nullptr);
    softmax_kernel<<<dim3(512, 3), 256>>>(nullptr);
    gemm_pv_mma<<<dim3(4, 4, 24), 256, SMEM_PV>>>(ea, eb, ec, out);
    beta_b2a_kernel<<<dim3(8, 3), 512>>>(ea, eb, ec);
    tail_kernel<<<dim3(512, 8, 3), 128>>>(ea, eb, ec, out);
}